// round 1
// baseline (speedup 1.0000x reference)
#include <cuda_runtime.h>
#include <math_constants.h>

#define NTOK 4096
#define DMODEL 1024
#define NH 16
#define HD 64

// Scratch (allocation-free rule: device globals)
__device__ float g_Q[NH * NTOK * HD];   // [h][n][d]
__device__ float g_K[NH * NTOK * HD];
__device__ float g_V[NH * NTOK * HD];
__device__ float g_H[NTOK * DMODEL];    // [n][h*HD+d]

// ---------------------------------------------------------------------------
// Tiled fp32 GEMM: C = A[4096,1024] @ B[1024,1024]
// BM=BN=128, BK=16, 256 threads, 8x8 per thread (cols split tx*4 and tx*4+64
// for conflict-free LDS.128).
// HEADOUT=1: write C into [h][n][d] layout; HEADOUT=0: plain row-major.
// ---------------------------------------------------------------------------
template <int HEADOUT>
__global__ __launch_bounds__(256, 2)
void gemm_f32(const float* __restrict__ A, const float* __restrict__ Bw,
              float* __restrict__ C) {
    const int K = DMODEL, Nc = DMODEL;
    __shared__ float As[16][128];  // As[k][m]
    __shared__ float Bs[16][128];  // Bs[k][n]

    const int bm = blockIdx.y * 128;
    const int bn = blockIdx.x * 128;
    const int tid = threadIdx.x;
    const int ty = tid >> 4;       // 0..15 -> rows ty*8..+8
    const int tx = tid & 15;       // 0..15 -> cols tx*4 and 64+tx*4

    float acc[8][8];
#pragma unroll
    for (int i = 0; i < 8; i++)
#pragma unroll
        for (int j = 0; j < 8; j++) acc[i][j] = 0.f;

    for (int k0 = 0; k0 < K; k0 += 16) {
#pragma unroll
        for (int t = 0; t < 2; t++) {
            int q = tid + t * 256;              // 0..511
            // A tile: [128 rows][16 cols] -> store transposed
            int ra = q >> 2, ca = (q & 3) * 4;
            float4 va = *(const float4*)&A[(size_t)(bm + ra) * K + k0 + ca];
            As[ca + 0][ra] = va.x; As[ca + 1][ra] = va.y;
            As[ca + 2][ra] = va.z; As[ca + 3][ra] = va.w;
            // B tile: [16 rows][128 cols]
            int rb = q >> 5, cb = (q & 31) * 4;
            float4 vb = *(const float4*)&Bw[(size_t)(k0 + rb) * Nc + bn + cb];
            *(float4*)&Bs[rb][cb] = vb;
        }
        __syncthreads();

#pragma unroll
        for (int kk = 0; kk < 16; kk++) {
            float a[8], b[8];
            *(float4*)(a)     = *(float4*)&As[kk][ty * 8];
            *(float4*)(a + 4) = *(float4*)&As[kk][ty * 8 + 4];
            *(float4*)(b)     = *(float4*)&Bs[kk][tx * 4];
            *(float4*)(b + 4) = *(float4*)&Bs[kk][tx * 4 + 64];
#pragma unroll
            for (int i = 0; i < 8; i++)
#pragma unroll
                for (int j = 0; j < 8; j++) acc[i][j] = fmaf(a[i], b[j], acc[i][j]);
        }
        __syncthreads();
    }

#pragma unroll
    for (int i = 0; i < 8; i++) {
        int m = bm + ty * 8 + i;
#pragma unroll
        for (int j = 0; j < 8; j++) {
            int c = (j < 4) ? (bn + tx * 4 + j) : (bn + 64 + tx * 4 + (j - 4));
            if (HEADOUT) {
                int h = c >> 6, d = c & 63;
                C[(size_t)h * (NTOK * HD) + (size_t)m * HD + d] = acc[i][j];
            } else {
                C[(size_t)m * Nc + c] = acc[i][j];
            }
        }
    }
}

// ---------------------------------------------------------------------------
// Flash attention, fp32. BQ=BS=64, head_dim=64, 256 threads, 4x4 acc/thread.
// Grid: (NTOK/64, NH). Scores never hit HBM; online softmax.
// ---------------------------------------------------------------------------
#define FA_PAD 65
#define FA_SMEM ((4 * 64 * FA_PAD + 3 * 64) * (int)sizeof(float))

__global__ __launch_bounds__(256)
void flash_attn(const float* __restrict__ Q, const float* __restrict__ Kg,
                const float* __restrict__ Vg, float* __restrict__ H) {
    extern __shared__ float sm[];
    float* Qs   = sm;                    // 64 x 65
    float* Ks   = Qs + 64 * FA_PAD;      // 64 x 65
    float* Vs   = Ks + 64 * FA_PAD;      // 64 x 65
    float* Ss   = Vs + 64 * FA_PAD;      // 64 x 65
    float* mrow = Ss + 64 * FA_PAD;      // 64
    float* lrow = mrow + 64;             // 64
    float* arow = lrow + 64;             // 64

    const int qt = blockIdx.x;
    const int h  = blockIdx.y;
    const int tid = threadIdx.x;
    const int ty = tid >> 4, tx = tid & 15;
    const int r0 = ty * 4, d0 = tx * 4;

    const float* Qh = Q  + (size_t)h * (NTOK * HD) + (size_t)qt * 64 * HD;
    const float* Kh = Kg + (size_t)h * (NTOK * HD);
    const float* Vh = Vg + (size_t)h * (NTOK * HD);

    // Load Q tile (4096 floats)
#pragma unroll
    for (int t = 0; t < 4; t++) {
        int q = tid + t * 256;
        int r = q >> 4, c = (q & 15) * 4;
        float4 v = *(const float4*)&Qh[r * HD + c];
        Qs[r * FA_PAD + c + 0] = v.x; Qs[r * FA_PAD + c + 1] = v.y;
        Qs[r * FA_PAD + c + 2] = v.z; Qs[r * FA_PAD + c + 3] = v.w;
    }
    if (tid < 64) { mrow[tid] = -CUDART_INF_F; lrow[tid] = 0.f; }

    float acc[4][4];
#pragma unroll
    for (int i = 0; i < 4; i++)
#pragma unroll
        for (int j = 0; j < 4; j++) acc[i][j] = 0.f;

    for (int s = 0; s < NTOK / 64; s++) {
        __syncthreads();  // previous iter done with Ks/Vs/Ss
#pragma unroll
        for (int t = 0; t < 4; t++) {
            int q = tid + t * 256;
            int r = q >> 4, c = (q & 15) * 4;
            float4 kv = *(const float4*)&Kh[(size_t)(s * 64 + r) * HD + c];
            Ks[r * FA_PAD + c + 0] = kv.x; Ks[r * FA_PAD + c + 1] = kv.y;
            Ks[r * FA_PAD + c + 2] = kv.z; Ks[r * FA_PAD + c + 3] = kv.w;
            float4 vv = *(const float4*)&Vh[(size_t)(s * 64 + r) * HD + c];
            Vs[r * FA_PAD + c + 0] = vv.x; Vs[r * FA_PAD + c + 1] = vv.y;
            Vs[r * FA_PAD + c + 2] = vv.z; Vs[r * FA_PAD + c + 3] = vv.w;
        }
        __syncthreads();

        // S = (Q K^T) * 1/sqrt(64)
        float sacc[4][4];
#pragma unroll
        for (int i = 0; i < 4; i++)
#pragma unroll
            for (int j = 0; j < 4; j++) sacc[i][j] = 0.f;
#pragma unroll 8
        for (int k = 0; k < 64; k++) {
            float a[4], b[4];
#pragma unroll
            for (int i = 0; i < 4; i++) a[i] = Qs[(r0 + i) * FA_PAD + k];
#pragma unroll
            for (int j = 0; j < 4; j++) b[j] = Ks[(d0 + j) * FA_PAD + k];
#pragma unroll
            for (int i = 0; i < 4; i++)
#pragma unroll
                for (int j = 0; j < 4; j++) sacc[i][j] = fmaf(a[i], b[j], sacc[i][j]);
        }
#pragma unroll
        for (int i = 0; i < 4; i++)
#pragma unroll
            for (int j = 0; j < 4; j++)
                Ss[(r0 + i) * FA_PAD + d0 + j] = sacc[i][j] * 0.125f;
        __syncthreads();

        // Online-softmax row statistics (64 rows by 64 threads)
        if (tid < 64) {
            int r = tid;
            float mx = mrow[r];
#pragma unroll 8
            for (int c = 0; c < 64; c++) mx = fmaxf(mx, Ss[r * FA_PAD + c]);
            float alpha = __expf(mrow[r] - mx);
            float sum = 0.f;
#pragma unroll 8
            for (int c = 0; c < 64; c++) {
                float p = __expf(Ss[r * FA_PAD + c] - mx);
                Ss[r * FA_PAD + c] = p;
                sum += p;
            }
            lrow[r] = lrow[r] * alpha + sum;
            mrow[r] = mx;
            arow[r] = alpha;
        }
        __syncthreads();

        // Rescale + accumulate O += P @ V
        float al[4];
#pragma unroll
        for (int i = 0; i < 4; i++) al[i] = arow[r0 + i];
#pragma unroll
        for (int i = 0; i < 4; i++)
#pragma unroll
            for (int j = 0; j < 4; j++) acc[i][j] *= al[i];
#pragma unroll 8
        for (int k = 0; k < 64; k++) {
            float p[4], v[4];
#pragma unroll
            for (int i = 0; i < 4; i++) p[i] = Ss[(r0 + i) * FA_PAD + k];
#pragma unroll
            for (int j = 0; j < 4; j++) v[j] = Vs[k * FA_PAD + d0 + j];
#pragma unroll
            for (int i = 0; i < 4; i++)
#pragma unroll
                for (int j = 0; j < 4; j++) acc[i][j] = fmaf(p[i], v[j], acc[i][j]);
        }
    }
    __syncthreads();

    // Epilogue: H[n][h*64+d] = acc / l
#pragma unroll
    for (int i = 0; i < 4; i++) {
        float inv = 1.f / lrow[r0 + i];
        int n = qt * 64 + r0 + i;
#pragma unroll
        for (int j = 0; j < 4; j++)
            H[(size_t)n * DMODEL + h * HD + d0 + j] = acc[i][j] * inv;
    }
}

// ---------------------------------------------------------------------------
extern "C" void kernel_launch(void* const* d_in, const int* in_sizes, int n_in,
                              void* d_out, int out_size) {
    const float* q  = (const float*)d_in[0];
    const float* k  = (const float*)d_in[1];
    const float* v  = (const float*)d_in[2];
    const float* Wq = (const float*)d_in[3];
    const float* Wk = (const float*)d_in[4];
    const float* Wv = (const float*)d_in[5];
    const float* Wo = (const float*)d_in[6];

    float *Qp, *Kp, *Vp, *Hp;
    cudaGetSymbolAddress((void**)&Qp, g_Q);
    cudaGetSymbolAddress((void**)&Kp, g_K);
    cudaGetSymbolAddress((void**)&Vp, g_V);
    cudaGetSymbolAddress((void**)&Hp, g_H);

    cudaFuncSetAttribute(flash_attn,
                         cudaFuncAttributeMaxDynamicSharedMemorySize, FA_SMEM);

    dim3 gproj(DMODEL / 128, NTOK / 128);  // (8, 32)
    gemm_f32<1><<<gproj, 256>>>(q, Wq, Qp);
    gemm_f32<1><<<gproj, 256>>>(k, Wk, Kp);
    gemm_f32<1><<<gproj, 256>>>(v, Wv, Vp);

    flash_attn<<<dim3(NTOK / 64, NH), 256, FA_SMEM>>>(Qp, Kp, Vp, Hp);

    gemm_f32<0><<<gproj, 256>>>(Hp, Wo, (float*)d_out);
}

// round 3
// speedup vs baseline: 2.6633x; 2.6633x over previous
#include <cuda_runtime.h>
#include <math_constants.h>
#include <cstdint>

#define NTOK 4096
#define DMODEL 1024
#define NH 16
#define HD 64

// Scratch (allocation-free rule: device globals)
__device__ float g_Q[NH * NTOK * HD];   // [h][n][d]
__device__ float g_K[NH * NTOK * HD];
__device__ float g_V[NH * NTOK * HD];
__device__ float g_H[NTOK * DMODEL];    // [n][h*HD+d]

// ---------------------------------------------------------------------------
// tf32 helpers
// ---------------------------------------------------------------------------
__device__ __forceinline__ float f2tf32(float x) {
    float r;
    asm("cvt.rna.tf32.f32 %0, %1;" : "=f"(r) : "f"(x));
    return r;
}
__device__ __forceinline__ float4 cvt4(float4 v) {
    v.x = f2tf32(v.x); v.y = f2tf32(v.y); v.z = f2tf32(v.z); v.w = f2tf32(v.w);
    return v;
}

// D += A*B, m16n8k8, A row-major (16x8), B col-major (8x8), f32 accum.
// a/b registers hold tf32 bit patterns.
__device__ __forceinline__ void mma8(float c[4], const uint32_t a[4],
                                     const uint32_t b[2]) {
    asm volatile(
        "mma.sync.aligned.m16n8k8.row.col.f32.tf32.tf32.f32 "
        "{%0,%1,%2,%3},{%4,%5,%6,%7},{%8,%9},{%0,%1,%2,%3};"
        : "+f"(c[0]), "+f"(c[1]), "+f"(c[2]), "+f"(c[3])
        : "r"(a[0]), "r"(a[1]), "r"(a[2]), "r"(a[3]), "r"(b[0]), "r"(b[1]));
}
#define F2U(x) __float_as_uint(x)

// ============================================================================
// GEMM: C[4096,1024] = A[4096,1024] @ B[1024,1024]  (tf32 mma.sync)
// CTA tile 128x128, BK=32, 8 warps (2m x 4n), warp tile 64x32.
// A smem: [128][SA=36] (stride%32==4 -> conflict-free a-frag loads)
// B smem: [32][SB=136] (stride%32==8 -> conflict-free b-frag loads)
// Double-buffered, register prefetch, one __syncthreads per K-chunk.
// ============================================================================
#define SA 36
#define SB 136
#define ABUF (128 * SA)          // floats
#define BBUF (32 * SB)
#define GSMEM ((2 * ABUF + 2 * BBUF) * (int)sizeof(float))  // 71680 B

template <int HEADOUT>
__global__ __launch_bounds__(256, 2)
void gemm_mma(const float* __restrict__ A, const float* __restrict__ Bw,
              float* __restrict__ C) {
    extern __shared__ float sm[];
    float* As[2] = {sm, sm + ABUF};
    float* Bs[2] = {sm + 2 * ABUF, sm + 2 * ABUF + BBUF};

    const int tid  = threadIdx.x;
    const int wid  = tid >> 5, lane = tid & 31;
    const int wm   = wid >> 2;          // 0..1
    const int wn   = wid & 3;           // 0..3
    const int g    = lane >> 2;         // 0..7
    const int lq   = lane & 3;          // 0..3
    const int bm   = blockIdx.y * 128;
    const int bn   = blockIdx.x * 128;

    float acc[4][4][4];                 // [mt][nt][4]
#pragma unroll
    for (int i = 0; i < 4; i++)
#pragma unroll
        for (int j = 0; j < 4; j++)
#pragma unroll
            for (int r = 0; r < 4; r++) acc[i][j][r] = 0.f;

    // staging index precompute
    const int ar = tid >> 1, ac = (tid & 1) * 4;        // wrong shape; use loops below

    float4 ra[4], rb[4];
    // prologue: load chunk 0
#pragma unroll
    for (int t = 0; t < 4; t++) {
        int q = t * 256 + tid;
        int row = q >> 3, kc = (q & 7) * 4;
        ra[t] = *(const float4*)(A + (size_t)(bm + row) * DMODEL + kc);
        int kr = q >> 5, nc = (q & 31) * 4;
        rb[t] = *(const float4*)(Bw + (size_t)kr * DMODEL + bn + nc);
    }
#pragma unroll
    for (int t = 0; t < 4; t++) {
        int q = t * 256 + tid;
        int row = q >> 3, kc = (q & 7) * 4;
        *(float4*)(As[0] + row * SA + kc) = cvt4(ra[t]);
        int kr = q >> 5, nc = (q & 31) * 4;
        *(float4*)(Bs[0] + kr * SB + nc) = cvt4(rb[t]);
    }
    __syncthreads();

    for (int c = 0; c < 32; c++) {
        const int cur = c & 1;
        if (c < 31) {
            const int k0 = (c + 1) * 32;
#pragma unroll
            for (int t = 0; t < 4; t++) {
                int q = t * 256 + tid;
                int row = q >> 3, kc = (q & 7) * 4;
                ra[t] = *(const float4*)(A + (size_t)(bm + row) * DMODEL + k0 + kc);
                int kr = q >> 5, nc = (q & 31) * 4;
                rb[t] = *(const float4*)(Bw + (size_t)(k0 + kr) * DMODEL + bn + nc);
            }
        }
        const float* Ab = As[cur];
        const float* Bb = Bs[cur];
#pragma unroll
        for (int ks = 0; ks < 4; ks++) {
            const int kk = ks * 8 + lq;
            uint32_t b[4][2];
#pragma unroll
            for (int nt = 0; nt < 4; nt++) {
                int n0 = wn * 32 + nt * 8 + g;
                b[nt][0] = F2U(Bb[kk * SB + n0]);
                b[nt][1] = F2U(Bb[(kk + 4) * SB + n0]);
            }
#pragma unroll
            for (int mt = 0; mt < 4; mt++) {
                int m0 = wm * 64 + mt * 16 + g;
                uint32_t a[4];
                a[0] = F2U(Ab[m0 * SA + kk]);
                a[1] = F2U(Ab[(m0 + 8) * SA + kk]);
                a[2] = F2U(Ab[m0 * SA + kk + 4]);
                a[3] = F2U(Ab[(m0 + 8) * SA + kk + 4]);
#pragma unroll
                for (int nt = 0; nt < 4; nt++) mma8(acc[mt][nt], a, b[nt]);
            }
        }
        if (c < 31) {
#pragma unroll
            for (int t = 0; t < 4; t++) {
                int q = t * 256 + tid;
                int row = q >> 3, kc = (q & 7) * 4;
                *(float4*)(As[cur ^ 1] + row * SA + kc) = cvt4(ra[t]);
                int kr = q >> 5, nc = (q & 31) * 4;
                *(float4*)(Bs[cur ^ 1] + kr * SB + nc) = cvt4(rb[t]);
            }
        }
        __syncthreads();
    }

    // Epilogue: float2 stores (c0,c1) and (c2,c3)
#pragma unroll
    for (int mt = 0; mt < 4; mt++) {
#pragma unroll
        for (int nt = 0; nt < 4; nt++) {
            int r0 = bm + wm * 64 + mt * 16 + g;
            int cc = bn + wn * 32 + nt * 8 + 2 * lq;
            float2 v0 = {acc[mt][nt][0], acc[mt][nt][1]};
            float2 v1 = {acc[mt][nt][2], acc[mt][nt][3]};
            if (HEADOUT) {
                int h = cc >> 6, d = cc & 63;
                *(float2*)(C + (size_t)h * (NTOK * HD) + (size_t)r0 * HD + d) = v0;
                *(float2*)(C + (size_t)h * (NTOK * HD) + (size_t)(r0 + 8) * HD + d) = v1;
            } else {
                *(float2*)(C + (size_t)r0 * DMODEL + cc) = v0;
                *(float2*)(C + (size_t)(r0 + 8) * DMODEL + cc) = v1;
            }
        }
    }
}

// ============================================================================
// Flash attention with tf32 mma.sync. BQ=BS=64, 256 threads (8 warps: 4m x 2n).
// Qs/Ks/Ss stride 68 (%32==4), Vs stride 72 (%32==8) -> conflict-free frags.
// O kept in registers; alpha-rescale via known c-fragment row mapping.
// ============================================================================
#define SQ 68
#define SV 72
#define Q_OFF 0
#define K_OFF (64 * SQ)
#define S_OFF (2 * 64 * SQ)
#define V_OFF (3 * 64 * SQ)
#define M_OFF (3 * 64 * SQ + 64 * SV)
#define FA_SMEM ((M_OFF + 3 * 64) * (int)sizeof(float))

__global__ __launch_bounds__(256, 2)
void flash_mma(const float* __restrict__ Q, const float* __restrict__ Kg,
               const float* __restrict__ Vg, float* __restrict__ H) {
    extern __shared__ float sm[];
    float* Qs = sm + Q_OFF;
    float* Ks = sm + K_OFF;
    float* Ss = sm + S_OFF;
    float* Vs = sm + V_OFF;
    float* mrow = sm + M_OFF;
    float* lrow = mrow + 64;
    float* arow = lrow + 64;

    const int qt = blockIdx.x, h = blockIdx.y;
    const int tid = threadIdx.x;
    const int wid = tid >> 5, lane = tid & 31;
    const int wm = wid & 3;            // m tile 0..3 (rows wm*16)
    const int wn = wid >> 2;           // n half 0..1 (cols wn*32)
    const int g = lane >> 2, lq = lane & 3;
    const int m0 = wm * 16;

    const float* Qh = Q  + (size_t)h * (NTOK * HD) + (size_t)qt * 64 * HD;
    const float* Kh = Kg + (size_t)h * (NTOK * HD);
    const float* Vh = Vg + (size_t)h * (NTOK * HD);

    // Stage Q (tf32)
#pragma unroll
    for (int t = 0; t < 4; t++) {
        int q = t * 256 + tid;
        int r = q >> 4, c = (q & 15) * 4;
        *(float4*)(Qs + r * SQ + c) = cvt4(*(const float4*)(Qh + r * HD + c));
    }
    if (tid < 64) { mrow[tid] = -CUDART_INF_F; lrow[tid] = 0.f; }

    float ofrag[4][4];
#pragma unroll
    for (int nt = 0; nt < 4; nt++)
#pragma unroll
        for (int r = 0; r < 4; r++) ofrag[nt][r] = 0.f;

    // Prefetch K/V tile 0
    float4 rk[4], rv[4];
#pragma unroll
    for (int t = 0; t < 4; t++) {
        int q = t * 256 + tid;
        int r = q >> 4, c = (q & 15) * 4;
        rk[t] = *(const float4*)(Kh + (size_t)r * HD + c);
        rv[t] = *(const float4*)(Vh + (size_t)r * HD + c);
    }

    for (int s = 0; s < NTOK / 64; s++) {
        __syncthreads();  // prev iter done reading Ks/Vs/Ss
#pragma unroll
        for (int t = 0; t < 4; t++) {
            int q = t * 256 + tid;
            int r = q >> 4, c = (q & 15) * 4;
            *(float4*)(Ks + r * SQ + c) = cvt4(rk[t]);
            *(float4*)(Vs + r * SV + c) = cvt4(rv[t]);
        }
        __syncthreads();
        if (s + 1 < NTOK / 64) {
#pragma unroll
            for (int t = 0; t < 4; t++) {
                int q = t * 256 + tid;
                int r = q >> 4, c = (q & 15) * 4;
                rk[t] = *(const float4*)(Kh + (size_t)((s + 1) * 64 + r) * HD + c);
                rv[t] = *(const float4*)(Vh + (size_t)((s + 1) * 64 + r) * HD + c);
            }
        }

        // --- S = Q K^T ---
        float sfr[4][4];
#pragma unroll
        for (int nt = 0; nt < 4; nt++)
#pragma unroll
            for (int r = 0; r < 4; r++) sfr[nt][r] = 0.f;
#pragma unroll
        for (int ks = 0; ks < 8; ks++) {
            const int kk = ks * 8 + lq;
            uint32_t a[4];
            a[0] = F2U(Qs[(m0 + g) * SQ + kk]);
            a[1] = F2U(Qs[(m0 + g + 8) * SQ + kk]);
            a[2] = F2U(Qs[(m0 + g) * SQ + kk + 4]);
            a[3] = F2U(Qs[(m0 + g + 8) * SQ + kk + 4]);
#pragma unroll
            for (int nt = 0; nt < 4; nt++) {
                int n0 = wn * 32 + nt * 8 + g;
                uint32_t b[2];
                b[0] = F2U(Ks[n0 * SQ + kk]);
                b[1] = F2U(Ks[n0 * SQ + kk + 4]);
                mma8(sfr[nt], a, b);
            }
        }
        // store S * 1/8
#pragma unroll
        for (int nt = 0; nt < 4; nt++) {
            int cc = wn * 32 + nt * 8 + 2 * lq;
            float2 v0 = {sfr[nt][0] * 0.125f, sfr[nt][1] * 0.125f};
            float2 v1 = {sfr[nt][2] * 0.125f, sfr[nt][3] * 0.125f};
            *(float2*)(Ss + (m0 + g) * SQ + cc) = v0;
            *(float2*)(Ss + (m0 + g + 8) * SQ + cc) = v1;
        }
        __syncthreads();

        // --- online softmax: 4 threads per row ---
        {
            int r = tid >> 2, gq = tid & 3;
            float mx = -CUDART_INF_F;
#pragma unroll
            for (int c = 0; c < 16; c++) mx = fmaxf(mx, Ss[r * SQ + gq * 16 + c]);
            mx = fmaxf(mx, __shfl_xor_sync(0xffffffffu, mx, 1));
            mx = fmaxf(mx, __shfl_xor_sync(0xffffffffu, mx, 2));
            float mold = mrow[r];
            float mnew = fmaxf(mold, mx);
            float sum = 0.f;
#pragma unroll
            for (int c = 0; c < 16; c++) {
                float p = __expf(Ss[r * SQ + gq * 16 + c] - mnew);
                Ss[r * SQ + gq * 16 + c] = f2tf32(p);
                sum += p;
            }
            sum += __shfl_xor_sync(0xffffffffu, sum, 1);
            sum += __shfl_xor_sync(0xffffffffu, sum, 2);
            if (gq == 0) {
                float alpha = __expf(mold - mnew);
                lrow[r] = lrow[r] * alpha + sum;
                mrow[r] = mnew;
                arow[r] = alpha;
            }
        }
        __syncthreads();

        // --- O = O*alpha + P V ---
        {
            float al0 = arow[m0 + g];
            float al1 = arow[m0 + 8 + g];
#pragma unroll
            for (int nt = 0; nt < 4; nt++) {
                ofrag[nt][0] *= al0; ofrag[nt][1] *= al0;
                ofrag[nt][2] *= al1; ofrag[nt][3] *= al1;
            }
        }
#pragma unroll
        for (int ks = 0; ks < 8; ks++) {
            const int kk = ks * 8;
            uint32_t a[4];
            a[0] = F2U(Ss[(m0 + g) * SQ + kk + lq]);
            a[1] = F2U(Ss[(m0 + g + 8) * SQ + kk + lq]);
            a[2] = F2U(Ss[(m0 + g) * SQ + kk + lq + 4]);
            a[3] = F2U(Ss[(m0 + g + 8) * SQ + kk + lq + 4]);
#pragma unroll
            for (int nt = 0; nt < 4; nt++) {
                int n0 = wn * 32 + nt * 8 + g;
                uint32_t b[2];
                b[0] = F2U(Vs[(kk + lq) * SV + n0]);
                b[1] = F2U(Vs[(kk + 4 + lq) * SV + n0]);
                mma8(ofrag[nt], a, b);
            }
        }
    }

    // Epilogue: divide by l, write H[n][h*64 + col]
    {
        float il0 = 1.f / lrow[m0 + g];
        float il1 = 1.f / lrow[m0 + 8 + g];
        int n0g = qt * 64 + m0 + g;
#pragma unroll
        for (int nt = 0; nt < 4; nt++) {
            int col = h * HD + wn * 32 + nt * 8 + 2 * lq;
            float2 v0 = {ofrag[nt][0] * il0, ofrag[nt][1] * il0};
            float2 v1 = {ofrag[nt][2] * il1, ofrag[nt][3] * il1};
            *(float2*)(H + (size_t)n0g * DMODEL + col) = v0;
            *(float2*)(H + (size_t)(n0g + 8) * DMODEL + col) = v1;
        }
    }
}

// ---------------------------------------------------------------------------
extern "C" void kernel_launch(void* const* d_in, const int* in_sizes, int n_in,
                              void* d_out, int out_size) {
    const float* q  = (const float*)d_in[0];
    const float* k  = (const float*)d_in[1];
    const float* v  = (const float*)d_in[2];
    const float* Wq = (const float*)d_in[3];
    const float* Wk = (const float*)d_in[4];
    const float* Wv = (const float*)d_in[5];
    const float* Wo = (const float*)d_in[6];

    float *Qp, *Kp, *Vp, *Hp;
    cudaGetSymbolAddress((void**)&Qp, g_Q);
    cudaGetSymbolAddress((void**)&Kp, g_K);
    cudaGetSymbolAddress((void**)&Vp, g_V);
    cudaGetSymbolAddress((void**)&Hp, g_H);

    cudaFuncSetAttribute(gemm_mma<1>,
                         cudaFuncAttributeMaxDynamicSharedMemorySize, GSMEM);
    cudaFuncSetAttribute(gemm_mma<0>,
                         cudaFuncAttributeMaxDynamicSharedMemorySize, GSMEM);
    cudaFuncSetAttribute(flash_mma,
                         cudaFuncAttributeMaxDynamicSharedMemorySize, FA_SMEM);

    dim3 gproj(DMODEL / 128, NTOK / 128);  // (8, 32)
    gemm_mma<1><<<gproj, 256, GSMEM>>>(q, Wq, Qp);
    gemm_mma<1><<<gproj, 256, GSMEM>>>(k, Wk, Kp);
    gemm_mma<1><<<gproj, 256, GSMEM>>>(v, Wv, Vp);

    flash_mma<<<dim3(NTOK / 64, NH), 256, FA_SMEM>>>(Qp, Kp, Vp, Hp);

    gemm_mma<0><<<gproj, 256, GSMEM>>>(Hp, Wo, (float*)d_out);
}

// round 4
// speedup vs baseline: 2.9811x; 1.1193x over previous
#include <cuda_runtime.h>
#include <math_constants.h>
#include <cstdint>

#define NTOK 4096
#define DMODEL 1024
#define NH 16
#define HD 64

// Scratch (allocation-free rule: device globals)
__device__ float g_Q[NH * NTOK * HD];   // [h][n][d]
__device__ float g_K[NH * NTOK * HD];
__device__ float g_V[NH * NTOK * HD];
__device__ float g_H[NTOK * DMODEL];    // [n][h*HD+d]

// ---------------------------------------------------------------------------
// tf32 helpers
// ---------------------------------------------------------------------------
__device__ __forceinline__ float f2tf32(float x) {
    float r;
    asm("cvt.rna.tf32.f32 %0, %1;" : "=f"(r) : "f"(x));
    return r;
}
__device__ __forceinline__ float4 cvt4(float4 v) {
    v.x = f2tf32(v.x); v.y = f2tf32(v.y); v.z = f2tf32(v.z); v.w = f2tf32(v.w);
    return v;
}

// D += A*B, m16n8k8, A row-major (16x8), B col-major (8x8), f32 accum.
__device__ __forceinline__ void mma8(float c[4], const uint32_t a[4],
                                     const uint32_t b[2]) {
    asm volatile(
        "mma.sync.aligned.m16n8k8.row.col.f32.tf32.tf32.f32 "
        "{%0,%1,%2,%3},{%4,%5,%6,%7},{%8,%9},{%0,%1,%2,%3};"
        : "+f"(c[0]), "+f"(c[1]), "+f"(c[2]), "+f"(c[3])
        : "r"(a[0]), "r"(a[1]), "r"(a[2]), "r"(a[3]), "r"(b[0]), "r"(b[1]));
}
#define F2U(x) __float_as_uint(x)

// ============================================================================
// GEMM: C[4096,1024] = A[4096,1024] @ B[1024,1024]  (tf32 mma.sync)
// (unchanged from round 3 — proven)
// ============================================================================
#define SA 36
#define SB 136
#define ABUF (128 * SA)
#define BBUF (32 * SB)
#define GSMEM ((2 * ABUF + 2 * BBUF) * (int)sizeof(float))

template <int HEADOUT>
__global__ __launch_bounds__(256, 2)
void gemm_mma(const float* __restrict__ A, const float* __restrict__ Bw,
              float* __restrict__ C) {
    extern __shared__ float sm[];
    float* As[2] = {sm, sm + ABUF};
    float* Bs[2] = {sm + 2 * ABUF, sm + 2 * ABUF + BBUF};

    const int tid  = threadIdx.x;
    const int wid  = tid >> 5, lane = tid & 31;
    const int wm   = wid >> 2;
    const int wn   = wid & 3;
    const int g    = lane >> 2;
    const int lq   = lane & 3;
    const int bm   = blockIdx.y * 128;
    const int bn   = blockIdx.x * 128;

    float acc[4][4][4];
#pragma unroll
    for (int i = 0; i < 4; i++)
#pragma unroll
        for (int j = 0; j < 4; j++)
#pragma unroll
            for (int r = 0; r < 4; r++) acc[i][j][r] = 0.f;

    float4 ra[4], rb[4];
#pragma unroll
    for (int t = 0; t < 4; t++) {
        int q = t * 256 + tid;
        int row = q >> 3, kc = (q & 7) * 4;
        ra[t] = *(const float4*)(A + (size_t)(bm + row) * DMODEL + kc);
        int kr = q >> 5, nc = (q & 31) * 4;
        rb[t] = *(const float4*)(Bw + (size_t)kr * DMODEL + bn + nc);
    }
#pragma unroll
    for (int t = 0; t < 4; t++) {
        int q = t * 256 + tid;
        int row = q >> 3, kc = (q & 7) * 4;
        *(float4*)(As[0] + row * SA + kc) = cvt4(ra[t]);
        int kr = q >> 5, nc = (q & 31) * 4;
        *(float4*)(Bs[0] + kr * SB + nc) = cvt4(rb[t]);
    }
    __syncthreads();

    for (int c = 0; c < 32; c++) {
        const int cur = c & 1;
        if (c < 31) {
            const int k0 = (c + 1) * 32;
#pragma unroll
            for (int t = 0; t < 4; t++) {
                int q = t * 256 + tid;
                int row = q >> 3, kc = (q & 7) * 4;
                ra[t] = *(const float4*)(A + (size_t)(bm + row) * DMODEL + k0 + kc);
                int kr = q >> 5, nc = (q & 31) * 4;
                rb[t] = *(const float4*)(Bw + (size_t)(k0 + kr) * DMODEL + bn + nc);
            }
        }
        const float* Ab = As[cur];
        const float* Bb = Bs[cur];
#pragma unroll
        for (int ks = 0; ks < 4; ks++) {
            const int kk = ks * 8 + lq;
            uint32_t b[4][2];
#pragma unroll
            for (int nt = 0; nt < 4; nt++) {
                int n0 = wn * 32 + nt * 8 + g;
                b[nt][0] = F2U(Bb[kk * SB + n0]);
                b[nt][1] = F2U(Bb[(kk + 4) * SB + n0]);
            }
#pragma unroll
            for (int mt = 0; mt < 4; mt++) {
                int m0 = wm * 64 + mt * 16 + g;
                uint32_t a[4];
                a[0] = F2U(Ab[m0 * SA + kk]);
                a[1] = F2U(Ab[(m0 + 8) * SA + kk]);
                a[2] = F2U(Ab[m0 * SA + kk + 4]);
                a[3] = F2U(Ab[(m0 + 8) * SA + kk + 4]);
#pragma unroll
                for (int nt = 0; nt < 4; nt++) mma8(acc[mt][nt], a, b[nt]);
            }
        }
        if (c < 31) {
#pragma unroll
            for (int t = 0; t < 4; t++) {
                int q = t * 256 + tid;
                int row = q >> 3, kc = (q & 7) * 4;
                *(float4*)(As[cur ^ 1] + row * SA + kc) = cvt4(ra[t]);
                int kr = q >> 5, nc = (q & 31) * 4;
                *(float4*)(Bs[cur ^ 1] + kr * SB + nc) = cvt4(rb[t]);
            }
        }
        __syncthreads();
    }

#pragma unroll
    for (int mt = 0; mt < 4; mt++) {
#pragma unroll
        for (int nt = 0; nt < 4; nt++) {
            int r0 = bm + wm * 64 + mt * 16 + g;
            int cc = bn + wn * 32 + nt * 8 + 2 * lq;
            float2 v0 = {acc[mt][nt][0], acc[mt][nt][1]};
            float2 v1 = {acc[mt][nt][2], acc[mt][nt][3]};
            if (HEADOUT) {
                int h = cc >> 6, d = cc & 63;
                *(float2*)(C + (size_t)h * (NTOK * HD) + (size_t)r0 * HD + d) = v0;
                *(float2*)(C + (size_t)h * (NTOK * HD) + (size_t)(r0 + 8) * HD + d) = v1;
            } else {
                *(float2*)(C + (size_t)r0 * DMODEL + cc) = v0;
                *(float2*)(C + (size_t)(r0 + 8) * DMODEL + cc) = v1;
            }
        }
    }
}

// ============================================================================
// Flash attention v2: register softmax, hoisted Q frags, shfl P frags.
// BQ=BS=64, 256 threads, warps: 4m x 2n. Each n-half warp owns 32 S-cols in
// regs; PV k-dim split across the pair; partial O summed in epilogue.
// Smem: Qs(64x68) | Ks(64x68) | Vs(64x72) | xbuf(2x64) | sbuf(2x64).
// obuf (epilogue) aliases Qs/Ks region with stride 36.
// ============================================================================
#define SQ 68
#define SV 72
#define FA_QOFF 0
#define FA_KOFF (64 * SQ)
#define FA_VOFF (2 * 64 * SQ)
#define FA_XOFF (2 * 64 * SQ + 64 * SV)
#define FA_SOFF (FA_XOFF + 128)
#define FA2_SMEM ((FA_SOFF + 128) * (int)sizeof(float))

__global__ __launch_bounds__(256, 2)
void flash_mma2(const float* __restrict__ Q, const float* __restrict__ Kg,
                const float* __restrict__ Vg, float* __restrict__ H) {
    extern __shared__ float sm[];
    float* Qs   = sm + FA_QOFF;
    float* Ks   = sm + FA_KOFF;
    float* Vs   = sm + FA_VOFF;
    float* xbuf = sm + FA_XOFF;
    float* sbuf = sm + FA_SOFF;
    float* obuf = sm;                       // epilogue alias (128 x 36 floats)

    const int qt = blockIdx.x, h = blockIdx.y;
    const int tid = threadIdx.x;
    const int wid = tid >> 5, lane = tid & 31;
    const int wm = wid & 3;                 // m tile (rows wm*16)
    const int wn = wid >> 2;                // n/k half
    const int g = lane >> 2, lq = lane & 3;
    const int m0 = wm * 16;
    const int base = lane & ~3;

    const float* Qh = Q  + (size_t)h * (NTOK * HD) + (size_t)qt * 64 * HD;
    const float* Kh = Kg + (size_t)h * (NTOK * HD);
    const float* Vh = Vg + (size_t)h * (NTOK * HD);

    // Stage Q, pre-scaled by 1/sqrt(64)=0.125 (exact power of 2)
#pragma unroll
    for (int t = 0; t < 4; t++) {
        int q = t * 256 + tid;
        int r = q >> 4, c = (q & 15) * 4;
        float4 v = *(const float4*)(Qh + (size_t)r * HD + c);
        v.x *= 0.125f; v.y *= 0.125f; v.z *= 0.125f; v.w *= 0.125f;
        *(float4*)(Qs + r * SQ + c) = cvt4(v);
    }
    __syncthreads();

    // Hoist Q fragments (invariant over the whole KV loop)
    uint32_t qa[8][4];
#pragma unroll
    for (int ks = 0; ks < 8; ks++) {
        const int kk = ks * 8 + lq;
        qa[ks][0] = F2U(Qs[(m0 + g) * SQ + kk]);
        qa[ks][1] = F2U(Qs[(m0 + g + 8) * SQ + kk]);
        qa[ks][2] = F2U(Qs[(m0 + g) * SQ + kk + 4]);
        qa[ks][3] = F2U(Qs[(m0 + g + 8) * SQ + kk + 4]);
    }

    float ofr[8][4];
#pragma unroll
    for (int nt = 0; nt < 8; nt++)
#pragma unroll
        for (int r = 0; r < 4; r++) ofr[nt][r] = 0.f;
    float mr0 = -CUDART_INF_F, mr1 = -CUDART_INF_F;
    float lr0 = 0.f, lr1 = 0.f;

    // Prefetch K tile 0
    float4 rk[4];
#pragma unroll
    for (int t = 0; t < 4; t++) {
        int q = t * 256 + tid;
        int r = q >> 4, c = (q & 15) * 4;
        rk[t] = *(const float4*)(Kh + (size_t)r * HD + c);
    }

    for (int s = 0; s < NTOK / 64; s++) {
        __syncthreads();  // A: Ks/Vs reuse guard
        // Stage K from prefetched regs
#pragma unroll
        for (int t = 0; t < 4; t++) {
            int q = t * 256 + tid;
            int r = q >> 4, c = (q & 15) * 4;
            *(float4*)(Ks + r * SQ + c) = cvt4(rk[t]);
        }
        // Issue V (this tile) and K (next tile) loads
        float4 rv[4];
#pragma unroll
        for (int t = 0; t < 4; t++) {
            int q = t * 256 + tid;
            int r = q >> 4, c = (q & 15) * 4;
            rv[t] = *(const float4*)(Vh + (size_t)(s * 64 + r) * HD + c);
        }
        if (s + 1 < NTOK / 64) {
#pragma unroll
            for (int t = 0; t < 4; t++) {
                int q = t * 256 + tid;
                int r = q >> 4, c = (q & 15) * 4;
                rk[t] = *(const float4*)(Kh + (size_t)((s + 1) * 64 + r) * HD + c);
            }
        }
        __syncthreads();  // B: Ks visible

        // --- S = Q K^T (registers) ---
        float sfr[4][4];
#pragma unroll
        for (int nt = 0; nt < 4; nt++)
#pragma unroll
            for (int r = 0; r < 4; r++) sfr[nt][r] = 0.f;
#pragma unroll
        for (int ks = 0; ks < 8; ks++) {
            const int kk = ks * 8 + lq;
#pragma unroll
            for (int nt = 0; nt < 4; nt++) {
                int n0 = wn * 32 + nt * 8 + g;
                uint32_t b[2];
                b[0] = F2U(Ks[n0 * SQ + kk]);
                b[1] = F2U(Ks[n0 * SQ + kk + 4]);
                mma8(sfr[nt], qa[ks], b);
            }
        }

        // --- partial row max (this warp's 32 cols) ---
        float pm0 = -CUDART_INF_F, pm1 = -CUDART_INF_F;
#pragma unroll
        for (int nt = 0; nt < 4; nt++) {
            pm0 = fmaxf(pm0, fmaxf(sfr[nt][0], sfr[nt][1]));
            pm1 = fmaxf(pm1, fmaxf(sfr[nt][2], sfr[nt][3]));
        }
        pm0 = fmaxf(pm0, __shfl_xor_sync(0xffffffffu, pm0, 1));
        pm0 = fmaxf(pm0, __shfl_xor_sync(0xffffffffu, pm0, 2));
        pm1 = fmaxf(pm1, __shfl_xor_sync(0xffffffffu, pm1, 1));
        pm1 = fmaxf(pm1, __shfl_xor_sync(0xffffffffu, pm1, 2));
        if (lq == 0) {
            xbuf[wn * 64 + m0 + g] = pm0;
            xbuf[wn * 64 + m0 + g + 8] = pm1;
        }
        // Stage V while max exchange is in flight
#pragma unroll
        for (int t = 0; t < 4; t++) {
            int q = t * 256 + tid;
            int r = q >> 4, c = (q & 15) * 4;
            *(float4*)(Vs + r * SV + c) = cvt4(rv[t]);
        }
        __syncthreads();  // C: xbuf + Vs visible

        float mn0 = fmaxf(mr0, fmaxf(pm0, xbuf[(wn ^ 1) * 64 + m0 + g]));
        float mn1 = fmaxf(mr1, fmaxf(pm1, xbuf[(wn ^ 1) * 64 + m0 + g + 8]));

        // --- exp in registers ---
        uint32_t p[4][4];
        float ps0 = 0.f, ps1 = 0.f;
#pragma unroll
        for (int nt = 0; nt < 4; nt++) {
            float e0 = __expf(sfr[nt][0] - mn0);
            float e1 = __expf(sfr[nt][1] - mn0);
            float e2 = __expf(sfr[nt][2] - mn1);
            float e3 = __expf(sfr[nt][3] - mn1);
            ps0 += e0 + e1; ps1 += e2 + e3;
            p[nt][0] = F2U(f2tf32(e0)); p[nt][1] = F2U(f2tf32(e1));
            p[nt][2] = F2U(f2tf32(e2)); p[nt][3] = F2U(f2tf32(e3));
        }
        ps0 += __shfl_xor_sync(0xffffffffu, ps0, 1);
        ps0 += __shfl_xor_sync(0xffffffffu, ps0, 2);
        ps1 += __shfl_xor_sync(0xffffffffu, ps1, 1);
        ps1 += __shfl_xor_sync(0xffffffffu, ps1, 2);
        if (lq == 0) {
            sbuf[wn * 64 + m0 + g] = ps0;
            sbuf[wn * 64 + m0 + g + 8] = ps1;
        }
        __syncthreads();  // D: sbuf visible

        float sum0 = ps0 + sbuf[(wn ^ 1) * 64 + m0 + g];
        float sum1 = ps1 + sbuf[(wn ^ 1) * 64 + m0 + g + 8];
        float al0 = __expf(mr0 - mn0);
        float al1 = __expf(mr1 - mn1);
        lr0 = lr0 * al0 + sum0;
        lr1 = lr1 * al1 + sum1;
        mr0 = mn0; mr1 = mn1;
#pragma unroll
        for (int nt = 0; nt < 8; nt++) {
            ofr[nt][0] *= al0; ofr[nt][1] *= al0;
            ofr[nt][2] *= al1; ofr[nt][3] *= al1;
        }

        // --- PV over this warp's k-half; P a-frags built via shfl ---
#pragma unroll
        for (int ks = 0; ks < 4; ks++) {
            const int s0 = base + (lq >> 1);
            const int s1 = s0 + 2;
            uint32_t t0 = __shfl_sync(0xffffffffu, p[ks][0], s0);
            uint32_t t1 = __shfl_sync(0xffffffffu, p[ks][1], s0);
            uint32_t t2 = __shfl_sync(0xffffffffu, p[ks][2], s0);
            uint32_t t3 = __shfl_sync(0xffffffffu, p[ks][3], s0);
            uint32_t u0 = __shfl_sync(0xffffffffu, p[ks][0], s1);
            uint32_t u1 = __shfl_sync(0xffffffffu, p[ks][1], s1);
            uint32_t u2 = __shfl_sync(0xffffffffu, p[ks][2], s1);
            uint32_t u3 = __shfl_sync(0xffffffffu, p[ks][3], s1);
            uint32_t pa[4];
            pa[0] = (lq & 1) ? t1 : t0;   // P[g][lq]
            pa[1] = (lq & 1) ? t3 : t2;   // P[g+8][lq]
            pa[2] = (lq & 1) ? u1 : u0;   // P[g][lq+4]
            pa[3] = (lq & 1) ? u3 : u2;   // P[g+8][lq+4]
            const int kr = wn * 32 + ks * 8 + lq;
#pragma unroll
            for (int nt = 0; nt < 8; nt++) {
                int n0 = nt * 8 + g;
                uint32_t b[2];
                b[0] = F2U(Vs[kr * SV + n0]);
                b[1] = F2U(Vs[(kr + 4) * SV + n0]);
                mma8(ofr[nt], pa, b);
            }
        }
    }

    // Epilogue: sum the two k-half partials, divide by l, store.
    __syncthreads();
    if (wn == 1) {
#pragma unroll
        for (int nt = 0; nt < 8; nt++)
            *(float4*)(obuf + (wm * 32 + lane) * 36 + nt * 4) = *(float4*)ofr[nt];
    }
    __syncthreads();
    if (wn == 0) {
        float il0 = 1.f / lr0, il1 = 1.f / lr1;
        int n0g = qt * 64 + m0 + g;
#pragma unroll
        for (int nt = 0; nt < 8; nt++) {
            float4 o = *(const float4*)(obuf + (wm * 32 + lane) * 36 + nt * 4);
            int col = h * HD + nt * 8 + 2 * lq;
            float2 v0 = {(ofr[nt][0] + o.x) * il0, (ofr[nt][1] + o.y) * il0};
            float2 v1 = {(ofr[nt][2] + o.z) * il1, (ofr[nt][3] + o.w) * il1};
            *(float2*)(H + (size_t)n0g * DMODEL + col) = v0;
            *(float2*)(H + (size_t)(n0g + 8) * DMODEL + col) = v1;
        }
    }
}

// ---------------------------------------------------------------------------
extern "C" void kernel_launch(void* const* d_in, const int* in_sizes, int n_in,
                              void* d_out, int out_size) {
    const float* q  = (const float*)d_in[0];
    const float* k  = (const float*)d_in[1];
    const float* v  = (const float*)d_in[2];
    const float* Wq = (const float*)d_in[3];
    const float* Wk = (const float*)d_in[4];
    const float* Wv = (const float*)d_in[5];
    const float* Wo = (const float*)d_in[6];

    float *Qp, *Kp, *Vp, *Hp;
    cudaGetSymbolAddress((void**)&Qp, g_Q);
    cudaGetSymbolAddress((void**)&Kp, g_K);
    cudaGetSymbolAddress((void**)&Vp, g_V);
    cudaGetSymbolAddress((void**)&Hp, g_H);

    cudaFuncSetAttribute(gemm_mma<1>,
                         cudaFuncAttributeMaxDynamicSharedMemorySize, GSMEM);
    cudaFuncSetAttribute(gemm_mma<0>,
                         cudaFuncAttributeMaxDynamicSharedMemorySize, GSMEM);
    cudaFuncSetAttribute(flash_mma2,
                         cudaFuncAttributeMaxDynamicSharedMemorySize, FA2_SMEM);

    dim3 gproj(DMODEL / 128, NTOK / 128);  // (8, 32)
    gemm_mma<1><<<gproj, 256, GSMEM>>>(q, Wq, Qp);
    gemm_mma<1><<<gproj, 256, GSMEM>>>(k, Wk, Kp);
    gemm_mma<1><<<gproj, 256, GSMEM>>>(v, Wv, Vp);

    flash_mma2<<<dim3(NTOK / 64, NH), 256, FA2_SMEM>>>(Qp, Kp, Vp, Hp);

    gemm_mma<0><<<gproj, 256, GSMEM>>>(Hp, Wo, (float*)d_out);
}

// round 5
// speedup vs baseline: 3.4691x; 1.1637x over previous
#include <cuda_runtime.h>
#include <math_constants.h>
#include <cstdint>

#define NTOK 4096
#define DMODEL 1024
#define NH 16
#define HD 64

// Scratch (allocation-free rule: device globals)
__device__ float g_Q[NH * NTOK * HD];   // [h][n][d]
__device__ float g_K[NH * NTOK * HD];
__device__ float g_V[NH * NTOK * HD];
__device__ float g_H[NTOK * DMODEL];    // [n][h*HD+d]

// ---------------------------------------------------------------------------
// helpers
// ---------------------------------------------------------------------------
__device__ __forceinline__ float f2tf32(float x) {
    float r;
    asm("cvt.rna.tf32.f32 %0, %1;" : "=f"(r) : "f"(x));
    return r;
}
__device__ __forceinline__ float4 cvt4(float4 v) {
    v.x = f2tf32(v.x); v.y = f2tf32(v.y); v.z = f2tf32(v.z); v.w = f2tf32(v.w);
    return v;
}
__device__ __forceinline__ float ex2f(float x) {
    float r;
    asm("ex2.approx.ftz.f32 %0, %1;" : "=f"(r) : "f"(x));
    return r;
}

// D += A*B, m16n8k8, A row-major (16x8), B col-major (8x8), f32 accum.
__device__ __forceinline__ void mma8(float c[4], const uint32_t a[4],
                                     const uint32_t b[2]) {
    asm volatile(
        "mma.sync.aligned.m16n8k8.row.col.f32.tf32.tf32.f32 "
        "{%0,%1,%2,%3},{%4,%5,%6,%7},{%8,%9},{%0,%1,%2,%3};"
        : "+f"(c[0]), "+f"(c[1]), "+f"(c[2]), "+f"(c[3])
        : "r"(a[0]), "r"(a[1]), "r"(a[2]), "r"(a[3]), "r"(b[0]), "r"(b[1]));
}
#define F2U(x) __float_as_uint(x)

// ============================================================================
// GEMM: C[4096,1024] = A[4096,1024] @ B[1024,1024]  (tf32 mma.sync)
// (unchanged — proven)
// ============================================================================
#define SA 36
#define SB 136
#define ABUF (128 * SA)
#define BBUF (32 * SB)
#define GSMEM ((2 * ABUF + 2 * BBUF) * (int)sizeof(float))

template <int HEADOUT>
__global__ __launch_bounds__(256, 2)
void gemm_mma(const float* __restrict__ A, const float* __restrict__ Bw,
              float* __restrict__ C) {
    extern __shared__ float sm[];
    float* As[2] = {sm, sm + ABUF};
    float* Bs[2] = {sm + 2 * ABUF, sm + 2 * ABUF + BBUF};

    const int tid  = threadIdx.x;
    const int wid  = tid >> 5, lane = tid & 31;
    const int wm   = wid >> 2;
    const int wn   = wid & 3;
    const int g    = lane >> 2;
    const int lq   = lane & 3;
    const int bm   = blockIdx.y * 128;
    const int bn   = blockIdx.x * 128;

    float acc[4][4][4];
#pragma unroll
    for (int i = 0; i < 4; i++)
#pragma unroll
        for (int j = 0; j < 4; j++)
#pragma unroll
            for (int r = 0; r < 4; r++) acc[i][j][r] = 0.f;

    float4 ra[4], rb[4];
#pragma unroll
    for (int t = 0; t < 4; t++) {
        int q = t * 256 + tid;
        int row = q >> 3, kc = (q & 7) * 4;
        ra[t] = *(const float4*)(A + (size_t)(bm + row) * DMODEL + kc);
        int kr = q >> 5, nc = (q & 31) * 4;
        rb[t] = *(const float4*)(Bw + (size_t)kr * DMODEL + bn + nc);
    }
#pragma unroll
    for (int t = 0; t < 4; t++) {
        int q = t * 256 + tid;
        int row = q >> 3, kc = (q & 7) * 4;
        *(float4*)(As[0] + row * SA + kc) = cvt4(ra[t]);
        int kr = q >> 5, nc = (q & 31) * 4;
        *(float4*)(Bs[0] + kr * SB + nc) = cvt4(rb[t]);
    }
    __syncthreads();

    for (int c = 0; c < 32; c++) {
        const int cur = c & 1;
        if (c < 31) {
            const int k0 = (c + 1) * 32;
#pragma unroll
            for (int t = 0; t < 4; t++) {
                int q = t * 256 + tid;
                int row = q >> 3, kc = (q & 7) * 4;
                ra[t] = *(const float4*)(A + (size_t)(bm + row) * DMODEL + k0 + kc);
                int kr = q >> 5, nc = (q & 31) * 4;
                rb[t] = *(const float4*)(Bw + (size_t)(k0 + kr) * DMODEL + bn + nc);
            }
        }
        const float* Ab = As[cur];
        const float* Bb = Bs[cur];
#pragma unroll
        for (int ks = 0; ks < 4; ks++) {
            const int kk = ks * 8 + lq;
            uint32_t b[4][2];
#pragma unroll
            for (int nt = 0; nt < 4; nt++) {
                int n0 = wn * 32 + nt * 8 + g;
                b[nt][0] = F2U(Bb[kk * SB + n0]);
                b[nt][1] = F2U(Bb[(kk + 4) * SB + n0]);
            }
#pragma unroll
            for (int mt = 0; mt < 4; mt++) {
                int m0 = wm * 64 + mt * 16 + g;
                uint32_t a[4];
                a[0] = F2U(Ab[m0 * SA + kk]);
                a[1] = F2U(Ab[(m0 + 8) * SA + kk]);
                a[2] = F2U(Ab[m0 * SA + kk + 4]);
                a[3] = F2U(Ab[(m0 + 8) * SA + kk + 4]);
#pragma unroll
                for (int nt = 0; nt < 4; nt++) mma8(acc[mt][nt], a, b[nt]);
            }
        }
        if (c < 31) {
#pragma unroll
            for (int t = 0; t < 4; t++) {
                int q = t * 256 + tid;
                int row = q >> 3, kc = (q & 7) * 4;
                *(float4*)(As[cur ^ 1] + row * SA + kc) = cvt4(ra[t]);
                int kr = q >> 5, nc = (q & 31) * 4;
                *(float4*)(Bs[cur ^ 1] + kr * SB + nc) = cvt4(rb[t]);
            }
        }
        __syncthreads();
    }

#pragma unroll
    for (int mt = 0; mt < 4; mt++) {
#pragma unroll
        for (int nt = 0; nt < 4; nt++) {
            int r0 = bm + wm * 64 + mt * 16 + g;
            int cc = bn + wn * 32 + nt * 8 + 2 * lq;
            float2 v0 = {acc[mt][nt][0], acc[mt][nt][1]};
            float2 v1 = {acc[mt][nt][2], acc[mt][nt][3]};
            if (HEADOUT) {
                int h = cc >> 6, d = cc & 63;
                *(float2*)(C + (size_t)h * (NTOK * HD) + (size_t)r0 * HD + d) = v0;
                *(float2*)(C + (size_t)h * (NTOK * HD) + (size_t)(r0 + 8) * HD + d) = v1;
            } else {
                *(float2*)(C + (size_t)r0 * DMODEL + cc) = v0;
                *(float2*)(C + (size_t)(r0 + 8) * DMODEL + cc) = v1;
            }
        }
    }
}

// ============================================================================
// Flash attention v3.
//  - K rows staged permuted by sigma(j)=2(j%4)+(j/4) within each 8-group, so
//    the QK C-fragment IS the PV A-fragment: a = {c0,c2,c1,c3}. Zero shfl.
//  - wn-halves keep independent (m,l,O) over their 32 S-cols; merged once in
//    the epilogue (split-KV combine). No per-iter cross-warp exchange.
//  - Q pre-scaled by 0.125*log2(e); softmax uses ex2.
//  - 3 barriers/iter: A (KV reuse guard), B (K ready), C (V ready).
// ============================================================================
#define SQ 68
#define SV 72
#define FA_QOFF 0
#define FA_KOFF (64 * SQ)
#define FA_VOFF (2 * 64 * SQ)
#define FA3_SMEM ((2 * 64 * SQ + 64 * SV) * (int)sizeof(float))

__global__ __launch_bounds__(256, 2)
void flash_mma3(const float* __restrict__ Q, const float* __restrict__ Kg,
                const float* __restrict__ Vg, float* __restrict__ H) {
    extern __shared__ float sm[];
    float* Qs = sm + FA_QOFF;
    float* Ks = sm + FA_KOFF;
    float* Vs = sm + FA_VOFF;

    const int qt = blockIdx.x, h = blockIdx.y;
    const int tid = threadIdx.x;
    const int wid = tid >> 5, lane = tid & 31;
    const int wm = wid & 3;                 // m tile (rows wm*16)
    const int wn = wid >> 2;                // S-column half / V k-half
    const int g = lane >> 2, lq = lane & 3;
    const int m0 = wm * 16;

    const float* Qh = Q  + (size_t)h * (NTOK * HD) + (size_t)qt * 64 * HD;
    const float* Kh = Kg + (size_t)h * (NTOK * HD);
    const float* Vh = Vg + (size_t)h * (NTOK * HD);

    // per-thread staging coords: handles rows r4s[t], cols cc..cc+3
    // Stage Q, pre-scaled by 0.125*log2(e)
    const float QSCALE = 0.125f * 1.4426950408889634f;
#pragma unroll
    for (int t = 0; t < 4; t++) {
        int q = t * 256 + tid;
        int r = q >> 4, c = (q & 15) * 4;
        float4 v = *(const float4*)(Qh + (size_t)r * HD + c);
        v.x *= QSCALE; v.y *= QSCALE; v.z *= QSCALE; v.w *= QSCALE;
        *(float4*)(Qs + r * SQ + c) = cvt4(v);
    }
    __syncthreads();

    // Hoist Q fragments
    uint32_t qa[8][4];
#pragma unroll
    for (int ks = 0; ks < 8; ks++) {
        const int kk = ks * 8 + lq;
        qa[ks][0] = F2U(Qs[(m0 + g) * SQ + kk]);
        qa[ks][1] = F2U(Qs[(m0 + g + 8) * SQ + kk]);
        qa[ks][2] = F2U(Qs[(m0 + g) * SQ + kk + 4]);
        qa[ks][3] = F2U(Qs[(m0 + g + 8) * SQ + kk + 4]);
    }

    float ofr[8][4];
#pragma unroll
    for (int nt = 0; nt < 8; nt++)
#pragma unroll
        for (int r = 0; r < 4; r++) ofr[nt][r] = 0.f;
    float mr0 = -CUDART_INF_F, mr1 = -CUDART_INF_F;
    float lr0 = 0.f, lr1 = 0.f;

    // Prefetch K tile 0
    float4 rk[4];
#pragma unroll
    for (int t = 0; t < 4; t++) {
        int q = t * 256 + tid;
        int r = q >> 4, c = (q & 15) * 4;
        rk[t] = *(const float4*)(Kh + (size_t)r * HD + c);
    }

    for (int s = 0; s < NTOK / 64; s++) {
        __syncthreads();  // A: Ks/Vs reuse guard
        // Stage K with sigma row permutation
#pragma unroll
        for (int t = 0; t < 4; t++) {
            int q = t * 256 + tid;
            int r = q >> 4, c = (q & 15) * 4;
            int rp = (r & ~7) | ((r & 3) << 1) | ((r >> 2) & 1);
            *(float4*)(Ks + rp * SQ + c) = cvt4(rk[t]);
        }
        // Issue V (this tile) and K (next tile) loads
        float4 rv[4];
#pragma unroll
        for (int t = 0; t < 4; t++) {
            int q = t * 256 + tid;
            int r = q >> 4, c = (q & 15) * 4;
            rv[t] = *(const float4*)(Vh + (size_t)(s * 64 + r) * HD + c);
        }
        if (s + 1 < NTOK / 64) {
#pragma unroll
            for (int t = 0; t < 4; t++) {
                int q = t * 256 + tid;
                int r = q >> 4, c = (q & 15) * 4;
                rk[t] = *(const float4*)(Kh + (size_t)((s + 1) * 64 + r) * HD + c);
            }
        }
        __syncthreads();  // B: Ks visible

        // --- S' = Q K'^T (columns sigma-permuted) ---
        float sfr[4][4];
#pragma unroll
        for (int nt = 0; nt < 4; nt++)
#pragma unroll
            for (int r = 0; r < 4; r++) sfr[nt][r] = 0.f;
#pragma unroll
        for (int ks = 0; ks < 8; ks++) {
            const int kk = ks * 8 + lq;
#pragma unroll
            for (int nt = 0; nt < 4; nt++) {
                int n0 = wn * 32 + nt * 8 + g;
                uint32_t b[2];
                b[0] = F2U(Ks[n0 * SQ + kk]);
                b[1] = F2U(Ks[n0 * SQ + kk + 4]);
                mma8(sfr[nt], qa[ks], b);
            }
        }

        // --- in-warp row stats over this half's 32 cols (log2 domain) ---
        float pm0 = -CUDART_INF_F, pm1 = -CUDART_INF_F;
#pragma unroll
        for (int nt = 0; nt < 4; nt++) {
            pm0 = fmaxf(pm0, fmaxf(sfr[nt][0], sfr[nt][1]));
            pm1 = fmaxf(pm1, fmaxf(sfr[nt][2], sfr[nt][3]));
        }
        pm0 = fmaxf(pm0, __shfl_xor_sync(0xffffffffu, pm0, 1));
        pm0 = fmaxf(pm0, __shfl_xor_sync(0xffffffffu, pm0, 2));
        pm1 = fmaxf(pm1, __shfl_xor_sync(0xffffffffu, pm1, 1));
        pm1 = fmaxf(pm1, __shfl_xor_sync(0xffffffffu, pm1, 2));
        float mn0 = fmaxf(mr0, pm0);
        float mn1 = fmaxf(mr1, pm1);

        // --- exp2 in registers; c-frag becomes PV a-frag (tf32 bits) ---
        uint32_t p[4][4];
        float ps0 = 0.f, ps1 = 0.f;
#pragma unroll
        for (int nt = 0; nt < 4; nt++) {
            float e0 = ex2f(sfr[nt][0] - mn0);
            float e1 = ex2f(sfr[nt][1] - mn0);
            float e2 = ex2f(sfr[nt][2] - mn1);
            float e3 = ex2f(sfr[nt][3] - mn1);
            ps0 += e0 + e1; ps1 += e2 + e3;
            p[nt][0] = F2U(f2tf32(e0)); p[nt][1] = F2U(f2tf32(e1));
            p[nt][2] = F2U(f2tf32(e2)); p[nt][3] = F2U(f2tf32(e3));
        }
        ps0 += __shfl_xor_sync(0xffffffffu, ps0, 1);
        ps0 += __shfl_xor_sync(0xffffffffu, ps0, 2);
        ps1 += __shfl_xor_sync(0xffffffffu, ps1, 1);
        ps1 += __shfl_xor_sync(0xffffffffu, ps1, 2);

        float al0 = ex2f(mr0 - mn0);
        float al1 = ex2f(mr1 - mn1);
        lr0 = lr0 * al0 + ps0;
        lr1 = lr1 * al1 + ps1;
        mr0 = mn0; mr1 = mn1;
#pragma unroll
        for (int nt = 0; nt < 8; nt++) {
            ofr[nt][0] *= al0; ofr[nt][1] *= al0;
            ofr[nt][2] *= al1; ofr[nt][3] *= al1;
        }

        // Stage V (unpermuted)
#pragma unroll
        for (int t = 0; t < 4; t++) {
            int q = t * 256 + tid;
            int r = q >> 4, c = (q & 15) * 4;
            *(float4*)(Vs + r * SV + c) = cvt4(rv[t]);
        }
        __syncthreads();  // C: Vs visible

        // --- O += P V over this half's 32 k-rows; a-frag = permuted c-frag ---
#pragma unroll
        for (int ks = 0; ks < 4; ks++) {
            uint32_t pa[4] = {p[ks][0], p[ks][2], p[ks][1], p[ks][3]};
            const int kr = wn * 32 + ks * 8 + lq;
#pragma unroll
            for (int nt = 0; nt < 8; nt++) {
                int n0 = nt * 8 + g;
                uint32_t b[2];
                b[0] = F2U(Vs[kr * SV + n0]);
                b[1] = F2U(Vs[(kr + 4) * SV + n0]);
                mma8(ofr[nt], pa, b);
            }
        }
    }

    // ---- Epilogue: merge the two wn halves (split-KV combine) ----
    __syncthreads();
    float* obuf = sm;                       // 64 rows x 66 floats (aliases Qs+)
    if (wn == 1) {
#pragma unroll
        for (int nt = 0; nt < 8; nt++) {
            *(float2*)(obuf + (m0 + g) * 66 + nt * 8 + 2 * lq) =
                make_float2(ofr[nt][0], ofr[nt][1]);
            *(float2*)(obuf + (m0 + 8 + g) * 66 + nt * 8 + 2 * lq) =
                make_float2(ofr[nt][2], ofr[nt][3]);
        }
        if (lq == 0) {
            *(float2*)(obuf + (m0 + g) * 66 + 64) = make_float2(mr0, lr0);
            *(float2*)(obuf + (m0 + 8 + g) * 66 + 64) = make_float2(mr1, lr1);
        }
    }
    __syncthreads();
    if (wn == 0) {
        float2 ml0 = *(const float2*)(obuf + (m0 + g) * 66 + 64);
        float2 ml1 = *(const float2*)(obuf + (m0 + 8 + g) * 66 + 64);
        float M0 = fmaxf(mr0, ml0.x);
        float M1 = fmaxf(mr1, ml1.x);
        float e00 = ex2f(mr0 - M0), e01 = ex2f(ml0.x - M0);
        float e10 = ex2f(mr1 - M1), e11 = ex2f(ml1.x - M1);
        float il0 = 1.f / (lr0 * e00 + ml0.y * e01);
        float il1 = 1.f / (lr1 * e10 + ml1.y * e11);
        int n0g = qt * 64 + m0 + g;
#pragma unroll
        for (int nt = 0; nt < 8; nt++) {
            float2 oa = *(const float2*)(obuf + (m0 + g) * 66 + nt * 8 + 2 * lq);
            float2 ob = *(const float2*)(obuf + (m0 + 8 + g) * 66 + nt * 8 + 2 * lq);
            int col = h * HD + nt * 8 + 2 * lq;
            float2 v0 = {(ofr[nt][0] * e00 + oa.x * e01) * il0,
                         (ofr[nt][1] * e00 + oa.y * e01) * il0};
            float2 v1 = {(ofr[nt][2] * e10 + ob.x * e11) * il1,
                         (ofr[nt][3] * e10 + ob.y * e11) * il1};
            *(float2*)(H + (size_t)n0g * DMODEL + col) = v0;
            *(float2*)(H + (size_t)(n0g + 8) * DMODEL + col) = v1;
        }
    }
}

// ---------------------------------------------------------------------------
extern "C" void kernel_launch(void* const* d_in, const int* in_sizes, int n_in,
                              void* d_out, int out_size) {
    const float* q  = (const float*)d_in[0];
    const float* k  = (const float*)d_in[1];
    const float* v  = (const float*)d_in[2];
    const float* Wq = (const float*)d_in[3];
    const float* Wk = (const float*)d_in[4];
    const float* Wv = (const float*)d_in[5];
    const float* Wo = (const float*)d_in[6];

    float *Qp, *Kp, *Vp, *Hp;
    cudaGetSymbolAddress((void**)&Qp, g_Q);
    cudaGetSymbolAddress((void**)&Kp, g_K);
    cudaGetSymbolAddress((void**)&Vp, g_V);
    cudaGetSymbolAddress((void**)&Hp, g_H);

    cudaFuncSetAttribute(gemm_mma<1>,
                         cudaFuncAttributeMaxDynamicSharedMemorySize, GSMEM);
    cudaFuncSetAttribute(gemm_mma<0>,
                         cudaFuncAttributeMaxDynamicSharedMemorySize, GSMEM);
    cudaFuncSetAttribute(flash_mma3,
                         cudaFuncAttributeMaxDynamicSharedMemorySize, FA3_SMEM);

    dim3 gproj(DMODEL / 128, NTOK / 128);  // (8, 32)
    gemm_mma<1><<<gproj, 256, GSMEM>>>(q, Wq, Qp);
    gemm_mma<1><<<gproj, 256, GSMEM>>>(k, Wk, Kp);
    gemm_mma<1><<<gproj, 256, GSMEM>>>(v, Wv, Vp);

    flash_mma3<<<dim3(NTOK / 64, NH), 256, FA3_SMEM>>>(Qp, Kp, Vp, Hp);

    gemm_mma<0><<<gproj, 256, GSMEM>>>(Hp, Wo, (float*)d_out);
}

// round 6
// speedup vs baseline: 5.3806x; 1.5510x over previous
#include <cuda_runtime.h>
#include <cuda_fp16.h>
#include <math_constants.h>
#include <cstdint>

#define NTOK 4096
#define DMODEL 1024
#define NH 16
#define HD 64

// Scratch (allocation-free rule: device globals)
__device__ float g_Q[NH * NTOK * HD];   // [h][n][d]
__device__ float g_K[NH * NTOK * HD];
__device__ float g_V[NH * NTOK * HD];
__device__ float g_H[NTOK * DMODEL];    // [n][h*HD+d]

// ---------------------------------------------------------------------------
// helpers
// ---------------------------------------------------------------------------
__device__ __forceinline__ uint32_t packh2(float x, float y) {
    __half2 h = __floats2half2_rn(x, y);
    return *(uint32_t*)&h;
}
__device__ __forceinline__ float ex2f(float x) {
    float r;
    asm("ex2.approx.ftz.f32 %0, %1;" : "=f"(r) : "f"(x));
    return r;
}

// D += A*B, m16n8k16, A row-major (16x16), B col-major (16x8), f32 accum.
__device__ __forceinline__ void mma16(float c[4], const uint32_t a[4],
                                      const uint32_t b[2]) {
    asm volatile(
        "mma.sync.aligned.m16n8k16.row.col.f32.f16.f16.f32 "
        "{%0,%1,%2,%3},{%4,%5,%6,%7},{%8,%9},{%0,%1,%2,%3};"
        : "+f"(c[0]), "+f"(c[1]), "+f"(c[2]), "+f"(c[3])
        : "r"(a[0]), "r"(a[1]), "r"(a[2]), "r"(a[3]), "r"(b[0]), "r"(b[1]));
}

// ============================================================================
// GEMM: C[4096,1024] = A[4096,1024] @ B[1024,1024]  (fp16 mma.sync, f32 acc)
// CTA tile 128x128, BK=32 (2 k16 steps), 8 warps (2m x 4n), warp tile 64x32.
// As: half[128][40]  (word-stride 20 -> conflict-free a-frags)
// Bp: half2-as-u32[16][136], Bp[k/2][n] = (B[2k][n], B[2k+1][n])
// Double-buffered, register prefetch, one __syncthreads per K-chunk.
// ============================================================================
#define GSA 40
#define GSB 136
#define GA_BYTES (128 * GSA * 2)          // 10240
#define GB_BYTES (16 * GSB * 4)           // 8704
#define GSMEM (2 * (GA_BYTES + GB_BYTES)) // 37888

template <int HEADOUT>
__global__ __launch_bounds__(256, 2)
void gemm_h(const float* __restrict__ A, const float* __restrict__ Bw,
            float* __restrict__ C) {
    extern __shared__ char smc[];
    __half* As[2] = {(__half*)smc, (__half*)(smc + GA_BYTES)};
    uint32_t* Bp[2] = {(uint32_t*)(smc + 2 * GA_BYTES),
                       (uint32_t*)(smc + 2 * GA_BYTES + GB_BYTES)};

    const int tid  = threadIdx.x;
    const int wid  = tid >> 5, lane = tid & 31;
    const int wm   = wid >> 2;          // 0..1
    const int wn   = wid & 3;           // 0..3
    const int g    = lane >> 2;
    const int lq   = lane & 3;
    const int bm   = blockIdx.y * 128;
    const int bn   = blockIdx.x * 128;

    float acc[4][4][4];
#pragma unroll
    for (int i = 0; i < 4; i++)
#pragma unroll
        for (int j = 0; j < 4; j++)
#pragma unroll
            for (int r = 0; r < 4; r++) acc[i][j][r] = 0.f;

    float4 ra[4], rb0[2], rb1[2];
    // prologue: load chunk 0
#pragma unroll
    for (int t = 0; t < 4; t++) {
        int q = t * 256 + tid;
        int row = q >> 3, kc = (q & 7) * 4;
        ra[t] = *(const float4*)(A + (size_t)(bm + row) * DMODEL + kc);
    }
#pragma unroll
    for (int t = 0; t < 2; t++) {
        int q = t * 256 + tid;
        int kk = q >> 5, cn = (q & 31) * 4;
        rb0[t] = *(const float4*)(Bw + (size_t)(2 * kk) * DMODEL + bn + cn);
        rb1[t] = *(const float4*)(Bw + (size_t)(2 * kk + 1) * DMODEL + bn + cn);
    }
#pragma unroll
    for (int t = 0; t < 4; t++) {
        int q = t * 256 + tid;
        int row = q >> 3, kc = (q & 7) * 4;
        uint2 w = {packh2(ra[t].x, ra[t].y), packh2(ra[t].z, ra[t].w)};
        *(uint2*)(As[0] + row * GSA + kc) = w;
    }
#pragma unroll
    for (int t = 0; t < 2; t++) {
        int q = t * 256 + tid;
        int kk = q >> 5, cn = (q & 31) * 4;
        Bp[0][kk * GSB + cn + 0] = packh2(rb0[t].x, rb1[t].x);
        Bp[0][kk * GSB + cn + 1] = packh2(rb0[t].y, rb1[t].y);
        Bp[0][kk * GSB + cn + 2] = packh2(rb0[t].z, rb1[t].z);
        Bp[0][kk * GSB + cn + 3] = packh2(rb0[t].w, rb1[t].w);
    }
    __syncthreads();

    for (int c = 0; c < 32; c++) {
        const int cur = c & 1;
        if (c < 31) {
            const int k0 = (c + 1) * 32;
#pragma unroll
            for (int t = 0; t < 4; t++) {
                int q = t * 256 + tid;
                int row = q >> 3, kc = (q & 7) * 4;
                ra[t] = *(const float4*)(A + (size_t)(bm + row) * DMODEL + k0 + kc);
            }
#pragma unroll
            for (int t = 0; t < 2; t++) {
                int q = t * 256 + tid;
                int kk = q >> 5, cn = (q & 31) * 4;
                rb0[t] = *(const float4*)(Bw + (size_t)(k0 + 2 * kk) * DMODEL + bn + cn);
                rb1[t] = *(const float4*)(Bw + (size_t)(k0 + 2 * kk + 1) * DMODEL + bn + cn);
            }
        }
        const __half* Ab = As[cur];
        const uint32_t* Bb = Bp[cur];
#pragma unroll
        for (int ks = 0; ks < 2; ks++) {
            uint32_t b[4][2];
#pragma unroll
            for (int nt = 0; nt < 4; nt++) {
                int n0 = wn * 32 + nt * 8 + g;
                b[nt][0] = Bb[(ks * 8 + lq) * GSB + n0];
                b[nt][1] = Bb[(ks * 8 + lq + 4) * GSB + n0];
            }
#pragma unroll
            for (int mt = 0; mt < 4; mt++) {
                int m0 = wm * 64 + mt * 16 + g;
                uint32_t a[4];
                a[0] = *(const uint32_t*)(Ab + m0 * GSA + ks * 16 + 2 * lq);
                a[1] = *(const uint32_t*)(Ab + (m0 + 8) * GSA + ks * 16 + 2 * lq);
                a[2] = *(const uint32_t*)(Ab + m0 * GSA + ks * 16 + 2 * lq + 8);
                a[3] = *(const uint32_t*)(Ab + (m0 + 8) * GSA + ks * 16 + 2 * lq + 8);
#pragma unroll
                for (int nt = 0; nt < 4; nt++) mma16(acc[mt][nt], a, b[nt]);
            }
        }
        if (c < 31) {
#pragma unroll
            for (int t = 0; t < 4; t++) {
                int q = t * 256 + tid;
                int row = q >> 3, kc = (q & 7) * 4;
                uint2 w = {packh2(ra[t].x, ra[t].y), packh2(ra[t].z, ra[t].w)};
                *(uint2*)(As[cur ^ 1] + row * GSA + kc) = w;
            }
#pragma unroll
            for (int t = 0; t < 2; t++) {
                int q = t * 256 + tid;
                int kk = q >> 5, cn = (q & 31) * 4;
                uint32_t* dst = (uint32_t*)Bp[cur ^ 1] + kk * GSB + cn;
                dst[0] = packh2(rb0[t].x, rb1[t].x);
                dst[1] = packh2(rb0[t].y, rb1[t].y);
                dst[2] = packh2(rb0[t].z, rb1[t].z);
                dst[3] = packh2(rb0[t].w, rb1[t].w);
            }
        }
        __syncthreads();
    }

    // Epilogue (C frag: c0,c1 = row g cols 2lq,2lq+1; c2,c3 = row g+8)
#pragma unroll
    for (int mt = 0; mt < 4; mt++) {
#pragma unroll
        for (int nt = 0; nt < 4; nt++) {
            int r0 = bm + wm * 64 + mt * 16 + g;
            int cc = bn + wn * 32 + nt * 8 + 2 * lq;
            float2 v0 = {acc[mt][nt][0], acc[mt][nt][1]};
            float2 v1 = {acc[mt][nt][2], acc[mt][nt][3]};
            if (HEADOUT) {
                int h = cc >> 6, d = cc & 63;
                *(float2*)(C + (size_t)h * (NTOK * HD) + (size_t)r0 * HD + d) = v0;
                *(float2*)(C + (size_t)h * (NTOK * HD) + (size_t)(r0 + 8) * HD + d) = v1;
            } else {
                *(float2*)(C + (size_t)r0 * DMODEL + cc) = v0;
                *(float2*)(C + (size_t)(r0 + 8) * DMODEL + cc) = v1;
            }
        }
    }
}

// ============================================================================
// Flash attention v4 (fp16 mma).
//  - f16 C-frag packs directly into f16 A-frag: P = half2(e0,e1). No permute,
//    no shuffle.
//  - wn halves keep independent (m,l,O) over their 32 S-cols; one epilogue
//    merge (split-KV combine).
//  - Q pre-scaled by 0.125*log2(e); ex2-based softmax.
//  - Qs/Ks: half[64][72]; Vp: u32[32][72], Vp[k/2][n]=(V[2k][n],V[2k+1][n]).
// ============================================================================
#define FSQ 72
#define FH_QOFF 0
#define FH_KOFF (64 * FSQ * 2)                    // 9216
#define FH_VOFF (2 * 64 * FSQ * 2)                // 18432
#define FH_SMEM (FH_VOFF + 32 * FSQ * 4)          // 27648

__global__ __launch_bounds__(256, 2)
void flash_h(const float* __restrict__ Q, const float* __restrict__ Kg,
             const float* __restrict__ Vg, float* __restrict__ H) {
    extern __shared__ char smc[];
    __half* Qs = (__half*)(smc + FH_QOFF);
    __half* Ks = (__half*)(smc + FH_KOFF);
    uint32_t* Vp = (uint32_t*)(smc + FH_VOFF);
    float* obuf = (float*)smc;                    // epilogue alias 64x66 f32

    const int qt = blockIdx.x, h = blockIdx.y;
    const int tid = threadIdx.x;
    const int wid = tid >> 5, lane = tid & 31;
    const int wm = wid & 3;                 // m tile (rows wm*16)
    const int wn = wid >> 2;                // S-column half / V k-half
    const int g = lane >> 2, lq = lane & 3;
    const int m0 = wm * 16;

    const float* Qh = Q  + (size_t)h * (NTOK * HD) + (size_t)qt * 64 * HD;
    const float* Kh = Kg + (size_t)h * (NTOK * HD);
    const float* Vh = Vg + (size_t)h * (NTOK * HD);

    // Stage Q, pre-scaled by 0.125*log2(e)
    const float QSCALE = 0.125f * 1.4426950408889634f;
#pragma unroll
    for (int t = 0; t < 4; t++) {
        int q = t * 256 + tid;
        int r = q >> 4, c = (q & 15) * 4;
        float4 v = *(const float4*)(Qh + (size_t)r * HD + c);
        uint2 w = {packh2(v.x * QSCALE, v.y * QSCALE),
                   packh2(v.z * QSCALE, v.w * QSCALE)};
        *(uint2*)(Qs + r * FSQ + c) = w;
    }
    __syncthreads();

    // Hoist Q fragments: qa[ks][4], ks over 4 k16-steps
    uint32_t qa[4][4];
#pragma unroll
    for (int ks = 0; ks < 4; ks++) {
        qa[ks][0] = *(const uint32_t*)(Qs + (m0 + g) * FSQ + ks * 16 + 2 * lq);
        qa[ks][1] = *(const uint32_t*)(Qs + (m0 + g + 8) * FSQ + ks * 16 + 2 * lq);
        qa[ks][2] = *(const uint32_t*)(Qs + (m0 + g) * FSQ + ks * 16 + 2 * lq + 8);
        qa[ks][3] = *(const uint32_t*)(Qs + (m0 + g + 8) * FSQ + ks * 16 + 2 * lq + 8);
    }

    float ofr[8][4];
#pragma unroll
    for (int nt = 0; nt < 8; nt++)
#pragma unroll
        for (int r = 0; r < 4; r++) ofr[nt][r] = 0.f;
    float mr0 = -CUDART_INF_F, mr1 = -CUDART_INF_F;
    float lr0 = 0.f, lr1 = 0.f;

    // Prefetch K tile 0
    float4 rk[4];
#pragma unroll
    for (int t = 0; t < 4; t++) {
        int q = t * 256 + tid;
        int r = q >> 4, c = (q & 15) * 4;
        rk[t] = *(const float4*)(Kh + (size_t)r * HD + c);
    }

    for (int s = 0; s < NTOK / 64; s++) {
        __syncthreads();  // A: Ks/Vp reuse guard
        // Stage K (row-major halves)
#pragma unroll
        for (int t = 0; t < 4; t++) {
            int q = t * 256 + tid;
            int r = q >> 4, c = (q & 15) * 4;
            uint2 w = {packh2(rk[t].x, rk[t].y), packh2(rk[t].z, rk[t].w)};
            *(uint2*)(Ks + r * FSQ + c) = w;
        }
        // Load V row-pairs (this tile) and prefetch K (next tile)
        float4 rv0[2], rv1[2];
#pragma unroll
        for (int t = 0; t < 2; t++) {
            int q = t * 256 + tid;
            int kk = q >> 4, c = (q & 15) * 4;
            rv0[t] = *(const float4*)(Vh + (size_t)(s * 64 + 2 * kk) * HD + c);
            rv1[t] = *(const float4*)(Vh + (size_t)(s * 64 + 2 * kk + 1) * HD + c);
        }
        if (s + 1 < NTOK / 64) {
#pragma unroll
            for (int t = 0; t < 4; t++) {
                int q = t * 256 + tid;
                int r = q >> 4, c = (q & 15) * 4;
                rk[t] = *(const float4*)(Kh + (size_t)((s + 1) * 64 + r) * HD + c);
            }
        }
        __syncthreads();  // B: Ks visible

        // --- S = Q K^T ---
        float sfr[4][4];
#pragma unroll
        for (int nt = 0; nt < 4; nt++)
#pragma unroll
            for (int r = 0; r < 4; r++) sfr[nt][r] = 0.f;
#pragma unroll
        for (int ks = 0; ks < 4; ks++) {
#pragma unroll
            for (int nt = 0; nt < 4; nt++) {
                int n0 = wn * 32 + nt * 8 + g;
                uint32_t b[2];
                b[0] = *(const uint32_t*)(Ks + n0 * FSQ + ks * 16 + 2 * lq);
                b[1] = *(const uint32_t*)(Ks + n0 * FSQ + ks * 16 + 2 * lq + 8);
                mma16(sfr[nt], qa[ks], b);
            }
        }

        // --- in-warp row stats over this half's 32 cols (log2 domain) ---
        float pm0 = -CUDART_INF_F, pm1 = -CUDART_INF_F;
#pragma unroll
        for (int nt = 0; nt < 4; nt++) {
            pm0 = fmaxf(pm0, fmaxf(sfr[nt][0], sfr[nt][1]));
            pm1 = fmaxf(pm1, fmaxf(sfr[nt][2], sfr[nt][3]));
        }
        pm0 = fmaxf(pm0, __shfl_xor_sync(0xffffffffu, pm0, 1));
        pm0 = fmaxf(pm0, __shfl_xor_sync(0xffffffffu, pm0, 2));
        pm1 = fmaxf(pm1, __shfl_xor_sync(0xffffffffu, pm1, 1));
        pm1 = fmaxf(pm1, __shfl_xor_sync(0xffffffffu, pm1, 2));
        float mn0 = fmaxf(mr0, pm0);
        float mn1 = fmaxf(mr1, pm1);

        // --- exp2; pack P into f16 A-fragments directly ---
        uint32_t p[4][2];
        float ps0 = 0.f, ps1 = 0.f;
#pragma unroll
        for (int nt = 0; nt < 4; nt++) {
            float e0 = ex2f(sfr[nt][0] - mn0);
            float e1 = ex2f(sfr[nt][1] - mn0);
            float e2 = ex2f(sfr[nt][2] - mn1);
            float e3 = ex2f(sfr[nt][3] - mn1);
            ps0 += e0 + e1; ps1 += e2 + e3;
            p[nt][0] = packh2(e0, e1);   // row g
            p[nt][1] = packh2(e2, e3);   // row g+8
        }
        ps0 += __shfl_xor_sync(0xffffffffu, ps0, 1);
        ps0 += __shfl_xor_sync(0xffffffffu, ps0, 2);
        ps1 += __shfl_xor_sync(0xffffffffu, ps1, 1);
        ps1 += __shfl_xor_sync(0xffffffffu, ps1, 2);

        float al0 = ex2f(mr0 - mn0);
        float al1 = ex2f(mr1 - mn1);
        lr0 = lr0 * al0 + ps0;
        lr1 = lr1 * al1 + ps1;
        mr0 = mn0; mr1 = mn1;
#pragma unroll
        for (int nt = 0; nt < 8; nt++) {
            ofr[nt][0] *= al0; ofr[nt][1] *= al0;
            ofr[nt][2] *= al1; ofr[nt][3] *= al1;
        }

        // Stage Vp (k-paired half2)
#pragma unroll
        for (int t = 0; t < 2; t++) {
            int q = t * 256 + tid;
            int kk = q >> 4, c = (q & 15) * 4;
            uint32_t* dst = Vp + kk * FSQ + c;
            dst[0] = packh2(rv0[t].x, rv1[t].x);
            dst[1] = packh2(rv0[t].y, rv1[t].y);
            dst[2] = packh2(rv0[t].z, rv1[t].z);
            dst[3] = packh2(rv0[t].w, rv1[t].w);
        }
        __syncthreads();  // C: Vp visible

        // --- O += P V over this half's 32 k-rows ---
#pragma unroll
        for (int kc = 0; kc < 2; kc++) {
            uint32_t pa[4] = {p[2 * kc][0], p[2 * kc][1],
                              p[2 * kc + 1][0], p[2 * kc + 1][1]};
            const int kr = wn * 16 + kc * 8 + lq;   // Vp row (half2 k-pairs)
#pragma unroll
            for (int nt = 0; nt < 8; nt++) {
                int n0 = nt * 8 + g;
                uint32_t b[2];
                b[0] = Vp[kr * FSQ + n0];
                b[1] = Vp[(kr + 4) * FSQ + n0];
                mma16(ofr[nt], pa, b);
            }
        }
    }

    // ---- Epilogue: merge the two wn halves (split-KV combine) ----
    __syncthreads();
    if (wn == 1) {
#pragma unroll
        for (int nt = 0; nt < 8; nt++) {
            *(float2*)(obuf + (m0 + g) * 66 + nt * 8 + 2 * lq) =
                make_float2(ofr[nt][0], ofr[nt][1]);
            *(float2*)(obuf + (m0 + 8 + g) * 66 + nt * 8 + 2 * lq) =
                make_float2(ofr[nt][2], ofr[nt][3]);
        }
        if (lq == 0) {
            *(float2*)(obuf + (m0 + g) * 66 + 64) = make_float2(mr0, lr0);
            *(float2*)(obuf + (m0 + 8 + g) * 66 + 64) = make_float2(mr1, lr1);
        }
    }
    __syncthreads();
    if (wn == 0) {
        float2 ml0 = *(const float2*)(obuf + (m0 + g) * 66 + 64);
        float2 ml1 = *(const float2*)(obuf + (m0 + 8 + g) * 66 + 64);
        float M0 = fmaxf(mr0, ml0.x);
        float M1 = fmaxf(mr1, ml1.x);
        float e00 = ex2f(mr0 - M0), e01 = ex2f(ml0.x - M0);
        float e10 = ex2f(mr1 - M1), e11 = ex2f(ml1.x - M1);
        float il0 = 1.f / (lr0 * e00 + ml0.y * e01);
        float il1 = 1.f / (lr1 * e10 + ml1.y * e11);
        int n0g = qt * 64 + m0 + g;
#pragma unroll
        for (int nt = 0; nt < 8; nt++) {
            float2 oa = *(const float2*)(obuf + (m0 + g) * 66 + nt * 8 + 2 * lq);
            float2 ob = *(const float2*)(obuf + (m0 + 8 + g) * 66 + nt * 8 + 2 * lq);
            int col = h * HD + nt * 8 + 2 * lq;
            float2 v0 = {(ofr[nt][0] * e00 + oa.x * e01) * il0,
                         (ofr[nt][1] * e00 + oa.y * e01) * il0};
            float2 v1 = {(ofr[nt][2] * e10 + ob.x * e11) * il1,
                         (ofr[nt][3] * e10 + ob.y * e11) * il1};
            *(float2*)(H + (size_t)n0g * DMODEL + col) = v0;
            *(float2*)(H + (size_t)(n0g + 8) * DMODEL + col) = v1;
        }
    }
}

// ---------------------------------------------------------------------------
extern "C" void kernel_launch(void* const* d_in, const int* in_sizes, int n_in,
                              void* d_out, int out_size) {
    const float* q  = (const float*)d_in[0];
    const float* k  = (const float*)d_in[1];
    const float* v  = (const float*)d_in[2];
    const float* Wq = (const float*)d_in[3];
    const float* Wk = (const float*)d_in[4];
    const float* Wv = (const float*)d_in[5];
    const float* Wo = (const float*)d_in[6];

    float *Qp, *Kp, *Vp, *Hp;
    cudaGetSymbolAddress((void**)&Qp, g_Q);
    cudaGetSymbolAddress((void**)&Kp, g_K);
    cudaGetSymbolAddress((void**)&Vp, g_V);
    cudaGetSymbolAddress((void**)&Hp, g_H);

    cudaFuncSetAttribute(gemm_h<1>,
                         cudaFuncAttributeMaxDynamicSharedMemorySize, GSMEM);
    cudaFuncSetAttribute(gemm_h<0>,
                         cudaFuncAttributeMaxDynamicSharedMemorySize, GSMEM);
    cudaFuncSetAttribute(flash_h,
                         cudaFuncAttributeMaxDynamicSharedMemorySize, FH_SMEM);

    dim3 gproj(DMODEL / 128, NTOK / 128);  // (8, 32)
    gemm_h<1><<<gproj, 256, GSMEM>>>(q, Wq, Qp);
    gemm_h<1><<<gproj, 256, GSMEM>>>(k, Wk, Kp);
    gemm_h<1><<<gproj, 256, GSMEM>>>(v, Wv, Vp);

    flash_h<<<dim3(NTOK / 64, NH), 256, FH_SMEM>>>(Qp, Kp, Vp, Hp);

    gemm_h<0><<<gproj, 256, GSMEM>>>(Hp, Wo, (float*)d_out);
}

// round 7
// speedup vs baseline: 6.2323x; 1.1583x over previous
#include <cuda_runtime.h>
#include <cuda_fp16.h>
#include <math_constants.h>
#include <cstdint>

#define NTOK 4096
#define DMODEL 1024
#define NH 16
#define HD 64

// fp16 scratch written by projection GEMMs (allocation-free rule: device globals)
__device__ __half g_Qh[NH * NTOK * HD];   // [h][n][d], pre-scaled by 0.125*log2e
__device__ __half g_Kh[NH * NTOK * HD];   // [h][n][d]
__device__ __half g_Vt[NH * HD * NTOK];   // [h][d][n]  (head-transposed)
__device__ float  g_H[NTOK * DMODEL];     // [n][h*HD+d]

#define QSCALE (0.125f * 1.4426950408889634f)

// ---------------------------------------------------------------------------
// helpers
// ---------------------------------------------------------------------------
__device__ __forceinline__ uint32_t packh2(float x, float y) {
    __half2 h = __floats2half2_rn(x, y);
    return *(uint32_t*)&h;
}
__device__ __forceinline__ float ex2f(float x) {
    float r;
    asm("ex2.approx.ftz.f32 %0, %1;" : "=f"(r) : "f"(x));
    return r;
}
__device__ __forceinline__ uint32_t smem_u32(const void* p) {
    uint32_t a;
    asm("{ .reg .u64 t; cvta.to.shared.u64 t, %1; cvt.u32.u64 %0, t; }"
        : "=r"(a) : "l"(p));
    return a;
}
__device__ __forceinline__ void cpa16(uint32_t dst, const void* src) {
    asm volatile("cp.async.cg.shared.global [%0], [%1], 16;"
                 :: "r"(dst), "l"(src) : "memory");
}
#define CP_COMMIT() asm volatile("cp.async.commit_group;" ::: "memory")
#define CP_WAIT1()  asm volatile("cp.async.wait_group 1;" ::: "memory")

// D += A*B, m16n8k16, f16 inputs, f32 accum.
__device__ __forceinline__ void mma16(float c[4], const uint32_t a[4],
                                      const uint32_t b[2]) {
    asm volatile(
        "mma.sync.aligned.m16n8k16.row.col.f32.f16.f16.f32 "
        "{%0,%1,%2,%3},{%4,%5,%6,%7},{%8,%9},{%0,%1,%2,%3};"
        : "+f"(c[0]), "+f"(c[1]), "+f"(c[2]), "+f"(c[3])
        : "r"(a[0]), "r"(a[1]), "r"(a[2]), "r"(a[3]), "r"(b[0]), "r"(b[1]));
}

// ============================================================================
// GEMM: C[4096,1024] = A[4096,1024](f32) @ B[1024,1024](f32), fp16 mma, f32 acc
// MODE 0: C f32 [n][1024]
// MODE 1: C half [h][n][d], scaled by QSCALE   (Q)
// MODE 2: C half [h][n][d]                      (K)
// MODE 3: C half [h][d][n] (head-transposed)    (V)
// ============================================================================
#define GSA 40
#define GSB 136
#define GA_BYTES (128 * GSA * 2)          // 10240
#define GB_BYTES (16 * GSB * 4)           // 8704
#define GSMEM (2 * (GA_BYTES + GB_BYTES)) // 37888

template <int MODE>
__global__ __launch_bounds__(256, 2)
void gemm_h(const float* __restrict__ A, const float* __restrict__ Bw,
            void* __restrict__ Cv) {
    extern __shared__ char smc[];
    __half* As[2] = {(__half*)smc, (__half*)(smc + GA_BYTES)};
    uint32_t* Bp[2] = {(uint32_t*)(smc + 2 * GA_BYTES),
                       (uint32_t*)(smc + 2 * GA_BYTES + GB_BYTES)};

    const int tid  = threadIdx.x;
    const int wid  = tid >> 5, lane = tid & 31;
    const int wm   = wid >> 2;
    const int wn   = wid & 3;
    const int g    = lane >> 2;
    const int lq   = lane & 3;
    const int bm   = blockIdx.y * 128;
    const int bn   = blockIdx.x * 128;

    float acc[4][4][4];
#pragma unroll
    for (int i = 0; i < 4; i++)
#pragma unroll
        for (int j = 0; j < 4; j++)
#pragma unroll
            for (int r = 0; r < 4; r++) acc[i][j][r] = 0.f;

    float4 ra[4], rb0[2], rb1[2];
#pragma unroll
    for (int t = 0; t < 4; t++) {
        int q = t * 256 + tid;
        int row = q >> 3, kc = (q & 7) * 4;
        ra[t] = *(const float4*)(A + (size_t)(bm + row) * DMODEL + kc);
    }
#pragma unroll
    for (int t = 0; t < 2; t++) {
        int q = t * 256 + tid;
        int kk = q >> 5, cn = (q & 31) * 4;
        rb0[t] = *(const float4*)(Bw + (size_t)(2 * kk) * DMODEL + bn + cn);
        rb1[t] = *(const float4*)(Bw + (size_t)(2 * kk + 1) * DMODEL + bn + cn);
    }
#pragma unroll
    for (int t = 0; t < 4; t++) {
        int q = t * 256 + tid;
        int row = q >> 3, kc = (q & 7) * 4;
        uint2 w = {packh2(ra[t].x, ra[t].y), packh2(ra[t].z, ra[t].w)};
        *(uint2*)(As[0] + row * GSA + kc) = w;
    }
#pragma unroll
    for (int t = 0; t < 2; t++) {
        int q = t * 256 + tid;
        int kk = q >> 5, cn = (q & 31) * 4;
        Bp[0][kk * GSB + cn + 0] = packh2(rb0[t].x, rb1[t].x);
        Bp[0][kk * GSB + cn + 1] = packh2(rb0[t].y, rb1[t].y);
        Bp[0][kk * GSB + cn + 2] = packh2(rb0[t].z, rb1[t].z);
        Bp[0][kk * GSB + cn + 3] = packh2(rb0[t].w, rb1[t].w);
    }
    __syncthreads();

    for (int c = 0; c < 32; c++) {
        const int cur = c & 1;
        if (c < 31) {
            const int k0 = (c + 1) * 32;
#pragma unroll
            for (int t = 0; t < 4; t++) {
                int q = t * 256 + tid;
                int row = q >> 3, kc = (q & 7) * 4;
                ra[t] = *(const float4*)(A + (size_t)(bm + row) * DMODEL + k0 + kc);
            }
#pragma unroll
            for (int t = 0; t < 2; t++) {
                int q = t * 256 + tid;
                int kk = q >> 5, cn = (q & 31) * 4;
                rb0[t] = *(const float4*)(Bw + (size_t)(k0 + 2 * kk) * DMODEL + bn + cn);
                rb1[t] = *(const float4*)(Bw + (size_t)(k0 + 2 * kk + 1) * DMODEL + bn + cn);
            }
        }
        const __half* Ab = As[cur];
        const uint32_t* Bb = Bp[cur];
#pragma unroll
        for (int ks = 0; ks < 2; ks++) {
            uint32_t b[4][2];
#pragma unroll
            for (int nt = 0; nt < 4; nt++) {
                int n0 = wn * 32 + nt * 8 + g;
                b[nt][0] = Bb[(ks * 8 + lq) * GSB + n0];
                b[nt][1] = Bb[(ks * 8 + lq + 4) * GSB + n0];
            }
#pragma unroll
            for (int mt = 0; mt < 4; mt++) {
                int m0 = wm * 64 + mt * 16 + g;
                uint32_t a[4];
                a[0] = *(const uint32_t*)(Ab + m0 * GSA + ks * 16 + 2 * lq);
                a[1] = *(const uint32_t*)(Ab + (m0 + 8) * GSA + ks * 16 + 2 * lq);
                a[2] = *(const uint32_t*)(Ab + m0 * GSA + ks * 16 + 2 * lq + 8);
                a[3] = *(const uint32_t*)(Ab + (m0 + 8) * GSA + ks * 16 + 2 * lq + 8);
#pragma unroll
                for (int nt = 0; nt < 4; nt++) mma16(acc[mt][nt], a, b[nt]);
            }
        }
        if (c < 31) {
#pragma unroll
            for (int t = 0; t < 4; t++) {
                int q = t * 256 + tid;
                int row = q >> 3, kc = (q & 7) * 4;
                uint2 w = {packh2(ra[t].x, ra[t].y), packh2(ra[t].z, ra[t].w)};
                *(uint2*)(As[cur ^ 1] + row * GSA + kc) = w;
            }
#pragma unroll
            for (int t = 0; t < 2; t++) {
                int q = t * 256 + tid;
                int kk = q >> 5, cn = (q & 31) * 4;
                uint32_t* dst = (uint32_t*)Bp[cur ^ 1] + kk * GSB + cn;
                dst[0] = packh2(rb0[t].x, rb1[t].x);
                dst[1] = packh2(rb0[t].y, rb1[t].y);
                dst[2] = packh2(rb0[t].z, rb1[t].z);
                dst[3] = packh2(rb0[t].w, rb1[t].w);
            }
        }
        __syncthreads();
    }

    // Epilogue
#pragma unroll
    for (int mt = 0; mt < 4; mt++) {
#pragma unroll
        for (int nt = 0; nt < 4; nt++) {
            int r0 = bm + wm * 64 + mt * 16 + g;
            int cc = bn + wn * 32 + nt * 8 + 2 * lq;
            if (MODE == 0) {
                float* C = (float*)Cv;
                *(float2*)(C + (size_t)r0 * DMODEL + cc) =
                    make_float2(acc[mt][nt][0], acc[mt][nt][1]);
                *(float2*)(C + (size_t)(r0 + 8) * DMODEL + cc) =
                    make_float2(acc[mt][nt][2], acc[mt][nt][3]);
            } else if (MODE == 1 || MODE == 2) {
                __half* C = (__half*)Cv;
                const float sc = (MODE == 1) ? QSCALE : 1.f;
                int h = cc >> 6, d = cc & 63;
                *(uint32_t*)(C + (size_t)h * (NTOK * HD) + (size_t)r0 * HD + d) =
                    packh2(acc[mt][nt][0] * sc, acc[mt][nt][1] * sc);
                *(uint32_t*)(C + (size_t)h * (NTOK * HD) + (size_t)(r0 + 8) * HD + d) =
                    packh2(acc[mt][nt][2] * sc, acc[mt][nt][3] * sc);
            } else {
                __half* C = (__half*)Cv;     // [h][d][ntok]
                int h = cc >> 6, d = cc & 63;
                size_t base = (size_t)h * (HD * NTOK);
                C[base + (size_t)d * NTOK + r0]           = __float2half(acc[mt][nt][0]);
                C[base + (size_t)(d + 1) * NTOK + r0]     = __float2half(acc[mt][nt][1]);
                C[base + (size_t)d * NTOK + r0 + 8]       = __float2half(acc[mt][nt][2]);
                C[base + (size_t)(d + 1) * NTOK + r0 + 8] = __float2half(acc[mt][nt][3]);
            }
        }
    }
}

// ============================================================================
// Flash attention v5: all-fp16 operands from gmem, cp.async 3-stage KV ring,
// one barrier per KV iter. Q frags hoisted; P = direct f16 C->A repack;
// split-softmax across wn halves merged once in epilogue.
// Smem: Qs half[64][72] | 3 stages x (Ks half[64][72] + Vts half[64][72]).
// ============================================================================
#define FSQ 72
#define FROWB (FSQ * 2)                       // 144 B row stride
#define TILEB (64 * FROWB)                    // 9216 B per K or V tile
#define FH_SMEM (TILEB + 3 * 2 * TILEB)       // 64512 B

__global__ __launch_bounds__(256, 2)
void flash_h2(const __half* __restrict__ Qg, const __half* __restrict__ Kg,
              const __half* __restrict__ Vt, float* __restrict__ H) {
    extern __shared__ char smc[];
    __half* Qs = (__half*)smc;
    const uint32_t sb = smem_u32(smc);
    float* obuf = (float*)smc;                // epilogue alias (64 x 66 f32)

    const int qt = blockIdx.x, h = blockIdx.y;
    const int tid = threadIdx.x;
    const int wid = tid >> 5, lane = tid & 31;
    const int wm = wid & 3;                   // m tile (rows wm*16)
    const int wn = wid >> 2;                  // S-column half / V k-half
    const int g = lane >> 2, lq = lane & 3;
    const int m0 = wm * 16;

    const __half* Qh  = Qg + (size_t)h * (NTOK * HD) + (size_t)qt * 64 * HD;
    const __half* Kh  = Kg + (size_t)h * (NTOK * HD);
    const __half* Vth = Vt + (size_t)h * (HD * NTOK);

    // Stage Q (already fp16 + pre-scaled)
#pragma unroll
    for (int t = 0; t < 2; t++) {
        int idx = t * 256 + tid;
        int row = idx >> 3, ch = idx & 7;
        *(uint4*)(Qs + row * FSQ + ch * 8) =
            *(const uint4*)(Qh + (size_t)row * HD + ch * 8);
    }

    // KV ring issue helper
    const int row = ((tid) >> 3) & 63;        // unused placeholder (kept simple below)
    auto issue_kv = [&](int buf, int s) {
        uint32_t kb = sb + TILEB + buf * (2 * TILEB);
        uint32_t vb = kb + TILEB;
#pragma unroll
        for (int t = 0; t < 2; t++) {
            int idx = t * 256 + tid;
            int r = idx >> 3, ch = idx & 7;
            cpa16(kb + r * FROWB + ch * 16,
                  Kh + (size_t)(s * 64 + r) * HD + ch * 8);
            cpa16(vb + r * FROWB + ch * 16,
                  Vth + (size_t)r * NTOK + s * 64 + ch * 8);
        }
    };

    issue_kv(0, 0); CP_COMMIT();
    issue_kv(1, 1); CP_COMMIT();
    __syncthreads();                           // Qs visible

    // Hoist Q fragments
    uint32_t qa[4][4];
#pragma unroll
    for (int ks = 0; ks < 4; ks++) {
        qa[ks][0] = *(const uint32_t*)(Qs + (m0 + g) * FSQ + ks * 16 + 2 * lq);
        qa[ks][1] = *(const uint32_t*)(Qs + (m0 + g + 8) * FSQ + ks * 16 + 2 * lq);
        qa[ks][2] = *(const uint32_t*)(Qs + (m0 + g) * FSQ + ks * 16 + 2 * lq + 8);
        qa[ks][3] = *(const uint32_t*)(Qs + (m0 + g + 8) * FSQ + ks * 16 + 2 * lq + 8);
    }

    float ofr[8][4];
#pragma unroll
    for (int nt = 0; nt < 8; nt++)
#pragma unroll
        for (int r = 0; r < 4; r++) ofr[nt][r] = 0.f;
    float mr0 = -CUDART_INF_F, mr1 = -CUDART_INF_F;
    float lr0 = 0.f, lr1 = 0.f;

    for (int s = 0; s < NTOK / 64; s++) {
        const int buf = s % 3;
        const __half* Ks  = (__half*)(smc + TILEB + buf * (2 * TILEB));
        const __half* Vts = Ks + 64 * FSQ;

        CP_WAIT1();
        __syncthreads();                       // tile s ready; prev compute done
        if (s + 2 < NTOK / 64) issue_kv((s + 2) % 3, s + 2);
        CP_COMMIT();                           // always commit (group-count invariant)

        // --- S = Q K^T ---
        float sfr[4][4];
#pragma unroll
        for (int nt = 0; nt < 4; nt++)
#pragma unroll
            for (int r = 0; r < 4; r++) sfr[nt][r] = 0.f;
#pragma unroll
        for (int ks = 0; ks < 4; ks++) {
#pragma unroll
            for (int nt = 0; nt < 4; nt++) {
                int n0 = wn * 32 + nt * 8 + g;
                uint32_t b[2];
                b[0] = *(const uint32_t*)(Ks + n0 * FSQ + ks * 16 + 2 * lq);
                b[1] = *(const uint32_t*)(Ks + n0 * FSQ + ks * 16 + 2 * lq + 8);
                mma16(sfr[nt], qa[ks], b);
            }
        }

        // --- row stats over this half's 32 cols (log2 domain) ---
        float pm0 = -CUDART_INF_F, pm1 = -CUDART_INF_F;
#pragma unroll
        for (int nt = 0; nt < 4; nt++) {
            pm0 = fmaxf(pm0, fmaxf(sfr[nt][0], sfr[nt][1]));
            pm1 = fmaxf(pm1, fmaxf(sfr[nt][2], sfr[nt][3]));
        }
        pm0 = fmaxf(pm0, __shfl_xor_sync(0xffffffffu, pm0, 1));
        pm0 = fmaxf(pm0, __shfl_xor_sync(0xffffffffu, pm0, 2));
        pm1 = fmaxf(pm1, __shfl_xor_sync(0xffffffffu, pm1, 1));
        pm1 = fmaxf(pm1, __shfl_xor_sync(0xffffffffu, pm1, 2));
        float mn0 = fmaxf(mr0, pm0);
        float mn1 = fmaxf(mr1, pm1);

        // --- exp2; pack P into f16 A-fragments ---
        uint32_t p[4][2];
        float ps0 = 0.f, ps1 = 0.f;
#pragma unroll
        for (int nt = 0; nt < 4; nt++) {
            float e0 = ex2f(sfr[nt][0] - mn0);
            float e1 = ex2f(sfr[nt][1] - mn0);
            float e2 = ex2f(sfr[nt][2] - mn1);
            float e3 = ex2f(sfr[nt][3] - mn1);
            ps0 += e0 + e1; ps1 += e2 + e3;
            p[nt][0] = packh2(e0, e1);
            p[nt][1] = packh2(e2, e3);
        }
        ps0 += __shfl_xor_sync(0xffffffffu, ps0, 1);
        ps0 += __shfl_xor_sync(0xffffffffu, ps0, 2);
        ps1 += __shfl_xor_sync(0xffffffffu, ps1, 1);
        ps1 += __shfl_xor_sync(0xffffffffu, ps1, 2);

        float al0 = ex2f(mr0 - mn0);
        float al1 = ex2f(mr1 - mn1);
        lr0 = lr0 * al0 + ps0;
        lr1 = lr1 * al1 + ps1;
        mr0 = mn0; mr1 = mn1;
#pragma unroll
        for (int nt = 0; nt < 8; nt++) {
            ofr[nt][0] *= al0; ofr[nt][1] *= al0;
            ofr[nt][2] *= al1; ofr[nt][3] *= al1;
        }

        // --- O += P V over this half's 32 kv rows (Vt: [d][token]) ---
#pragma unroll
        for (int kc = 0; kc < 2; kc++) {
            uint32_t pa[4] = {p[2 * kc][0], p[2 * kc][1],
                              p[2 * kc + 1][0], p[2 * kc + 1][1]};
            const int kr = wn * 16 + kc * 8 + lq;    // kv token-pair index
#pragma unroll
            for (int nt = 0; nt < 8; nt++) {
                int n0 = nt * 8 + g;                  // head-dim
                uint32_t b[2];
                b[0] = *(const uint32_t*)(Vts + n0 * FSQ + 2 * kr);
                b[1] = *(const uint32_t*)(Vts + n0 * FSQ + 2 * (kr + 4));
                mma16(ofr[nt], pa, b);
            }
        }
    }

    // ---- Epilogue: merge the two wn halves (split-KV combine) ----
    __syncthreads();
    if (wn == 1) {
#pragma unroll
        for (int nt = 0; nt < 8; nt++) {
            *(float2*)(obuf + (m0 + g) * 66 + nt * 8 + 2 * lq) =
                make_float2(ofr[nt][0], ofr[nt][1]);
            *(float2*)(obuf + (m0 + 8 + g) * 66 + nt * 8 + 2 * lq) =
                make_float2(ofr[nt][2], ofr[nt][3]);
        }
        if (lq == 0) {
            *(float2*)(obuf + (m0 + g) * 66 + 64) = make_float2(mr0, lr0);
            *(float2*)(obuf + (m0 + 8 + g) * 66 + 64) = make_float2(mr1, lr1);
        }
    }
    __syncthreads();
    if (wn == 0) {
        float2 ml0 = *(const float2*)(obuf + (m0 + g) * 66 + 64);
        float2 ml1 = *(const float2*)(obuf + (m0 + 8 + g) * 66 + 64);
        float M0 = fmaxf(mr0, ml0.x);
        float M1 = fmaxf(mr1, ml1.x);
        float e00 = ex2f(mr0 - M0), e01 = ex2f(ml0.x - M0);
        float e10 = ex2f(mr1 - M1), e11 = ex2f(ml1.x - M1);
        float il0 = 1.f / (lr0 * e00 + ml0.y * e01);
        float il1 = 1.f / (lr1 * e10 + ml1.y * e11);
        int n0g = qt * 64 + m0 + g;
#pragma unroll
        for (int nt = 0; nt < 8; nt++) {
            float2 oa = *(const float2*)(obuf + (m0 + g) * 66 + nt * 8 + 2 * lq);
            float2 ob = *(const float2*)(obuf + (m0 + 8 + g) * 66 + nt * 8 + 2 * lq);
            int col = h * HD + nt * 8 + 2 * lq;
            float2 v0 = {(ofr[nt][0] * e00 + oa.x * e01) * il0,
                         (ofr[nt][1] * e00 + oa.y * e01) * il0};
            float2 v1 = {(ofr[nt][2] * e10 + ob.x * e11) * il1,
                         (ofr[nt][3] * e10 + ob.y * e11) * il1};
            *(float2*)(H + (size_t)n0g * DMODEL + col) = v0;
            *(float2*)(H + (size_t)(n0g + 8) * DMODEL + col) = v1;
        }
    }
}

// ---------------------------------------------------------------------------
extern "C" void kernel_launch(void* const* d_in, const int* in_sizes, int n_in,
                              void* d_out, int out_size) {
    const float* q  = (const float*)d_in[0];
    const float* k  = (const float*)d_in[1];
    const float* v  = (const float*)d_in[2];
    const float* Wq = (const float*)d_in[3];
    const float* Wk = (const float*)d_in[4];
    const float* Wv = (const float*)d_in[5];
    const float* Wo = (const float*)d_in[6];

    __half *Qp, *Kp, *Vp;
    float *Hp;
    cudaGetSymbolAddress((void**)&Qp, g_Qh);
    cudaGetSymbolAddress((void**)&Kp, g_Kh);
    cudaGetSymbolAddress((void**)&Vp, g_Vt);
    cudaGetSymbolAddress((void**)&Hp, g_H);

    cudaFuncSetAttribute(gemm_h<0>, cudaFuncAttributeMaxDynamicSharedMemorySize, GSMEM);
    cudaFuncSetAttribute(gemm_h<1>, cudaFuncAttributeMaxDynamicSharedMemorySize, GSMEM);
    cudaFuncSetAttribute(gemm_h<2>, cudaFuncAttributeMaxDynamicSharedMemorySize, GSMEM);
    cudaFuncSetAttribute(gemm_h<3>, cudaFuncAttributeMaxDynamicSharedMemorySize, GSMEM);
    cudaFuncSetAttribute(flash_h2, cudaFuncAttributeMaxDynamicSharedMemorySize, FH_SMEM);

    dim3 gproj(DMODEL / 128, NTOK / 128);  // (8, 32)
    gemm_h<1><<<gproj, 256, GSMEM>>>(q, Wq, Qp);
    gemm_h<2><<<gproj, 256, GSMEM>>>(k, Wk, Kp);
    gemm_h<3><<<gproj, 256, GSMEM>>>(v, Wv, Vp);

    flash_h2<<<dim3(NTOK / 64, NH), 256, FH_SMEM>>>(Qp, Kp, Vp, Hp);

    gemm_h<0><<<gproj, 256, GSMEM>>>(Hp, Wo, d_out);
}

// round 8
// speedup vs baseline: 7.5413x; 1.2100x over previous
#include <cuda_runtime.h>
#include <cuda_fp16.h>
#include <math_constants.h>
#include <cstdint>

#define NTOK 4096
#define DMODEL 1024
#define NH 16
#define HD 64
#define QSCALE (0.125f * 1.4426950408889634f)

// ---------------- device scratch (allocation-free rule) ----------------
__device__ __half   g_qh[NTOK * DMODEL];           // fp16 activations
__device__ __half   g_kh[NTOK * DMODEL];
__device__ __half   g_vh[NTOK * DMODEL];
__device__ uint32_t g_Wqp[(DMODEL / 2) * DMODEL];  // k-paired weights
__device__ uint32_t g_Wkp[(DMODEL / 2) * DMODEL];
__device__ uint32_t g_Wvp[(DMODEL / 2) * DMODEL];
__device__ uint32_t g_Wop[(DMODEL / 2) * DMODEL];
__device__ __half   g_Qh[NH * NTOK * HD];          // [h][n][d], pre-scaled
__device__ __half   g_Kh[NH * NTOK * HD];          // [h][n][d]
__device__ __half   g_Vt[NH * HD * NTOK];          // [h][d][n]
__device__ __half   g_Hh[NTOK * DMODEL];           // attention out, fp16

// ---------------- helpers ----------------
__device__ __forceinline__ uint32_t packh2(float x, float y) {
    __half2 h = __floats2half2_rn(x, y);
    return *(uint32_t*)&h;
}
__device__ __forceinline__ float ex2f(float x) {
    float r;
    asm("ex2.approx.ftz.f32 %0, %1;" : "=f"(r) : "f"(x));
    return r;
}
__device__ __forceinline__ uint32_t smem_u32(const void* p) {
    uint32_t a;
    asm("{ .reg .u64 t; cvta.to.shared.u64 t, %1; cvt.u32.u64 %0, t; }"
        : "=r"(a) : "l"(p));
    return a;
}
__device__ __forceinline__ void cpa16(uint32_t dst, const void* src) {
    asm volatile("cp.async.cg.shared.global [%0], [%1], 16;"
                 :: "r"(dst), "l"(src) : "memory");
}
#define CP_COMMIT() asm volatile("cp.async.commit_group;" ::: "memory")
#define CP_WAIT1()  asm volatile("cp.async.wait_group 1;" ::: "memory")

#define LDSM4(r0, r1, r2, r3, addr) \
    asm volatile("ldmatrix.sync.aligned.m8n8.x4.shared.b16 {%0,%1,%2,%3}, [%4];" \
        : "=r"(r0), "=r"(r1), "=r"(r2), "=r"(r3) : "r"(addr))

__device__ __forceinline__ void mma16(float c[4], const uint32_t a[4],
                                      uint32_t b0, uint32_t b1) {
    asm volatile(
        "mma.sync.aligned.m16n8k16.row.col.f32.f16.f16.f32 "
        "{%0,%1,%2,%3},{%4,%5,%6,%7},{%8,%9},{%0,%1,%2,%3};"
        : "+f"(c[0]), "+f"(c[1]), "+f"(c[2]), "+f"(c[3])
        : "r"(a[0]), "r"(a[1]), "r"(a[2]), "r"(a[3]), "r"(b0), "r"(b1));
}

// ============================================================================
// Conversion kernels (run once per call, cheap)
// ============================================================================
__global__ __launch_bounds__(256)
void cvt_act(const float* __restrict__ q, const float* __restrict__ k,
             const float* __restrict__ v) {
    const int z = blockIdx.z;
    const float* src = (z == 0) ? q : (z == 1) ? k : v;
    __half* dst = (z == 0) ? g_qh : (z == 1) ? g_kh : g_vh;
    size_t i = ((size_t)blockIdx.x * 256 + threadIdx.x) * 8;
    float4 a = *(const float4*)(src + i);
    float4 b = *(const float4*)(src + i + 4);
    uint4 o = {packh2(a.x, a.y), packh2(a.z, a.w),
               packh2(b.x, b.y), packh2(b.z, b.w)};
    *(uint4*)(dst + i) = o;
}

__global__ __launch_bounds__(256)
void cvt_wgt(const float* __restrict__ Wq, const float* __restrict__ Wk,
             const float* __restrict__ Wv, const float* __restrict__ Wo) {
    const int z = blockIdx.z;
    const float* W = (z == 0) ? Wq : (z == 1) ? Wk : (z == 2) ? Wv : Wo;
    uint32_t* dst = (z == 0) ? g_Wqp : (z == 1) ? g_Wkp : (z == 2) ? g_Wvp : g_Wop;
    int idx = blockIdx.x * 256 + threadIdx.x;      // 131072 per z
    int kk = idx >> 8, c = (idx & 255) * 4;
    float4 r0 = *(const float4*)(W + (size_t)(2 * kk) * DMODEL + c);
    float4 r1 = *(const float4*)(W + (size_t)(2 * kk + 1) * DMODEL + c);
    uint4 o = {packh2(r0.x, r1.x), packh2(r0.y, r1.y),
               packh2(r0.z, r1.z), packh2(r0.w, r1.w)};
    *(uint4*)(dst + (size_t)kk * DMODEL + c) = o;
}

// ============================================================================
// GEMM v2: C[4096,1024] = A(fp16) @ B(paired u32), cp.async 3-stage ring.
// CTA 128x128, BK=32, 8 warps (2m x 4n). A-frags via ldmatrix.x4.
// fused=1: blockIdx.z selects (q,Wq)->g_Qh scaled / (k,Wk)->g_Kh / (v,Wv)->g_Vt.
// fused=0: A0/B0 params -> f32 Cout.
// ============================================================================
#define GSA 40                       // halves per A row (80 B)
#define GA_B 10240                   // 128*80
#define GB_B 8704                    // 16*136*4
#define GST (GA_B + GB_B)            // 18944
#define G_SMEM (3 * GST)             // 56832

__global__ __launch_bounds__(256, 2)
void gemm_fp16(const __half* __restrict__ A0, const uint32_t* __restrict__ B0,
               float* __restrict__ Cout, int fused) {
    extern __shared__ char smc[];
    const uint32_t sb = smem_u32(smc);
    const int tid = threadIdx.x, lane = tid & 31, wid = tid >> 5;
    const int wm = wid >> 2, wn = wid & 3;
    const int g = lane >> 2, lq = lane & 3;
    const int bm = blockIdx.y * 128, bn = blockIdx.x * 128;

    const __half* A;
    const uint32_t* Bg;
    int mode;
    if (fused) {
        int z = blockIdx.z;
        A = (z == 0) ? g_qh : (z == 1) ? g_kh : g_vh;
        Bg = (z == 0) ? g_Wqp : (z == 1) ? g_Wkp : g_Wvp;
        mode = z + 1;
    } else {
        A = A0; Bg = B0; mode = 0;
    }

    float acc[4][4][4];
#pragma unroll
    for (int i = 0; i < 4; i++)
#pragma unroll
        for (int j = 0; j < 4; j++)
#pragma unroll
            for (int r = 0; r < 4; r++) acc[i][j][r] = 0.f;

    auto issue = [&](int buf, int c) {
        uint32_t ab = sb + buf * GST;
        uint32_t bb = ab + GA_B;
#pragma unroll
        for (int t = 0; t < 2; t++) {
            int idx = t * 256 + tid;
            int row = idx >> 2, ch = idx & 3;
            cpa16(ab + row * 80 + ch * 16,
                  A + (size_t)(bm + row) * DMODEL + c * 32 + ch * 8);
        }
#pragma unroll
        for (int t = 0; t < 2; t++) {
            int idx = t * 256 + tid;
            int kk = idx >> 5, cn = (idx & 31) * 4;
            cpa16(bb + kk * 544 + cn * 4,
                  Bg + (size_t)(c * 16 + kk) * DMODEL + bn + cn);
        }
    };
    issue(0, 0); CP_COMMIT();
    issue(1, 1); CP_COMMIT();

    // ldmatrix lane mapping for A fragments
    const int mat = lane >> 3, rr = lane & 7;
    const int arow = wm * 64 + (mat & 1) * 8 + rr;
    const uint32_t akoff = (uint32_t)(lane >> 4) * 16;   // (mat>>1)*8 halves

    for (int c = 0; c < 32; c++) {
        const int st = c % 3;
        CP_WAIT1();
        __syncthreads();
        if (c + 2 < 32) issue((c + 2) % 3, c + 2);
        CP_COMMIT();

        uint32_t ab = sb + st * GST;
        const uint32_t* Bb = (const uint32_t*)(smc + st * GST + GA_B);

#pragma unroll
        for (int ks = 0; ks < 2; ks++) {
            uint32_t b[4][2];
#pragma unroll
            for (int nt = 0; nt < 4; nt++) {
                int n0 = wn * 32 + nt * 8 + g;
                b[nt][0] = Bb[(ks * 8 + lq) * 136 + n0];
                b[nt][1] = Bb[(ks * 8 + lq + 4) * 136 + n0];
            }
#pragma unroll
            for (int mt = 0; mt < 4; mt++) {
                uint32_t a[4];
                LDSM4(a[0], a[1], a[2], a[3],
                      ab + (uint32_t)(arow + mt * 16) * 80 + ks * 32 + akoff);
#pragma unroll
                for (int nt = 0; nt < 4; nt++)
                    mma16(acc[mt][nt], a, b[nt][0], b[nt][1]);
            }
        }
        __syncthreads();
    }

    // Epilogue
#pragma unroll
    for (int mt = 0; mt < 4; mt++) {
#pragma unroll
        for (int nt = 0; nt < 4; nt++) {
            int r0 = bm + wm * 64 + mt * 16 + g;
            int cc = bn + wn * 32 + nt * 8 + 2 * lq;
            if (mode == 0) {
                *(float2*)(Cout + (size_t)r0 * DMODEL + cc) =
                    make_float2(acc[mt][nt][0], acc[mt][nt][1]);
                *(float2*)(Cout + (size_t)(r0 + 8) * DMODEL + cc) =
                    make_float2(acc[mt][nt][2], acc[mt][nt][3]);
            } else if (mode == 1 || mode == 2) {
                __half* C = (mode == 1) ? g_Qh : g_Kh;
                const float sc = (mode == 1) ? QSCALE : 1.f;
                int h = cc >> 6, d = cc & 63;
                *(uint32_t*)(C + (size_t)h * (NTOK * HD) + (size_t)r0 * HD + d) =
                    packh2(acc[mt][nt][0] * sc, acc[mt][nt][1] * sc);
                *(uint32_t*)(C + (size_t)h * (NTOK * HD) + (size_t)(r0 + 8) * HD + d) =
                    packh2(acc[mt][nt][2] * sc, acc[mt][nt][3] * sc);
            } else {
                int h = cc >> 6, d = cc & 63;
                size_t base = (size_t)h * (HD * NTOK);
                g_Vt[base + (size_t)d * NTOK + r0]           = __float2half(acc[mt][nt][0]);
                g_Vt[base + (size_t)(d + 1) * NTOK + r0]     = __float2half(acc[mt][nt][1]);
                g_Vt[base + (size_t)d * NTOK + r0 + 8]       = __float2half(acc[mt][nt][2]);
                g_Vt[base + (size_t)(d + 1) * NTOK + r0 + 8] = __float2half(acc[mt][nt][3]);
            }
        }
    }
}

// ============================================================================
// Flash attention v6: ldmatrix b-frags (16 LDSM vs 64 LDS per warp/iter),
// cp.async 3-stage KV ring, alpha-skip, fp16 H output.
// ============================================================================
#define FSQ 72
#define FROWB (FSQ * 2)                    // 144 B
#define TILEB (64 * FROWB)                 // 9216 B
#define FH_SMEM (TILEB + 3 * 2 * TILEB)    // 64512 B

__global__ __launch_bounds__(256, 2)
void flash_h3() {
    extern __shared__ char smc[];
    __half* Qs = (__half*)smc;
    const uint32_t sb = smem_u32(smc);
    float* obuf = (float*)smc;             // epilogue alias (64 x 66 f32)

    const int qt = blockIdx.x, h = blockIdx.y;
    const int tid = threadIdx.x;
    const int wid = tid >> 5, lane = tid & 31;
    const int wm = wid & 3, wn = wid >> 2;
    const int g = lane >> 2, lq = lane & 3;
    const int m0 = wm * 16;
    const int mat = lane >> 3, rr = lane & 7;

    const __half* Qh  = g_Qh + (size_t)h * (NTOK * HD) + (size_t)qt * 64 * HD;
    const __half* Kh  = g_Kh + (size_t)h * (NTOK * HD);
    const __half* Vth = g_Vt + (size_t)h * (HD * NTOK);

    // Stage Q (fp16, pre-scaled)
#pragma unroll
    for (int t = 0; t < 2; t++) {
        int idx = t * 256 + tid;
        int row = idx >> 3, ch = idx & 7;
        *(uint4*)(Qs + row * FSQ + ch * 8) =
            *(const uint4*)(Qh + (size_t)row * HD + ch * 8);
    }

    auto issue_kv = [&](int buf, int s) {
        uint32_t kb = sb + TILEB + buf * (2 * TILEB);
        uint32_t vb = kb + TILEB;
#pragma unroll
        for (int t = 0; t < 2; t++) {
            int idx = t * 256 + tid;
            int r = idx >> 3, ch = idx & 7;
            cpa16(kb + r * FROWB + ch * 16,
                  Kh + (size_t)(s * 64 + r) * HD + ch * 8);
            cpa16(vb + r * FROWB + ch * 16,
                  Vth + (size_t)r * NTOK + s * 64 + ch * 8);
        }
    };
    issue_kv(0, 0); CP_COMMIT();
    issue_kv(1, 1); CP_COMMIT();
    __syncthreads();

    // Hoist Q fragments
    uint32_t qa[4][4];
#pragma unroll
    for (int ks = 0; ks < 4; ks++) {
        qa[ks][0] = *(const uint32_t*)(Qs + (m0 + g) * FSQ + ks * 16 + 2 * lq);
        qa[ks][1] = *(const uint32_t*)(Qs + (m0 + g + 8) * FSQ + ks * 16 + 2 * lq);
        qa[ks][2] = *(const uint32_t*)(Qs + (m0 + g) * FSQ + ks * 16 + 2 * lq + 8);
        qa[ks][3] = *(const uint32_t*)(Qs + (m0 + g + 8) * FSQ + ks * 16 + 2 * lq + 8);
    }

    // ldmatrix per-thread byte offsets
    const uint32_t koff0 =
        (uint32_t)((wn * 32 + (mat >> 1) * 8 + rr) * FSQ + (mat & 1) * 8) * 2;
    const uint32_t koff1 = koff0 + 16 * FSQ * 2;
    uint32_t voff[4];
#pragma unroll
    for (int j = 0; j < 4; j++)
        voff[j] = (uint32_t)(((2 * j + (mat >> 1)) * 8 + rr) * FSQ +
                             wn * 32 + (mat & 1) * 8) * 2;

    float ofr[8][4];
#pragma unroll
    for (int nt = 0; nt < 8; nt++)
#pragma unroll
        for (int r = 0; r < 4; r++) ofr[nt][r] = 0.f;
    float mr0 = -CUDART_INF_F, mr1 = -CUDART_INF_F;
    float lr0 = 0.f, lr1 = 0.f;

    for (int s = 0; s < NTOK / 64; s++) {
        const int buf = s % 3;
        const uint32_t kb = sb + TILEB + buf * (2 * TILEB);
        const uint32_t vb = kb + TILEB;

        CP_WAIT1();
        __syncthreads();
        if (s + 2 < NTOK / 64) issue_kv((s + 2) % 3, s + 2);
        CP_COMMIT();

        // --- S = Q K^T (b-frags via ldmatrix) ---
        float sfr[4][4];
#pragma unroll
        for (int nt = 0; nt < 4; nt++)
#pragma unroll
            for (int r = 0; r < 4; r++) sfr[nt][r] = 0.f;
#pragma unroll
        for (int ks = 0; ks < 4; ks++) {
            uint32_t b0, b1, b2, b3;
            LDSM4(b0, b1, b2, b3, kb + koff0 + ks * 32);
            mma16(sfr[0], qa[ks], b0, b1);
            mma16(sfr[1], qa[ks], b2, b3);
            LDSM4(b0, b1, b2, b3, kb + koff1 + ks * 32);
            mma16(sfr[2], qa[ks], b0, b1);
            mma16(sfr[3], qa[ks], b2, b3);
        }

        // --- row stats (log2 domain) ---
        float pm0 = -CUDART_INF_F, pm1 = -CUDART_INF_F;
#pragma unroll
        for (int nt = 0; nt < 4; nt++) {
            pm0 = fmaxf(pm0, fmaxf(sfr[nt][0], sfr[nt][1]));
            pm1 = fmaxf(pm1, fmaxf(sfr[nt][2], sfr[nt][3]));
        }
        pm0 = fmaxf(pm0, __shfl_xor_sync(0xffffffffu, pm0, 1));
        pm0 = fmaxf(pm0, __shfl_xor_sync(0xffffffffu, pm0, 2));
        pm1 = fmaxf(pm1, __shfl_xor_sync(0xffffffffu, pm1, 1));
        pm1 = fmaxf(pm1, __shfl_xor_sync(0xffffffffu, pm1, 2));
        float mn0 = fmaxf(mr0, pm0);
        float mn1 = fmaxf(mr1, pm1);
        bool upd = (mn0 > mr0) || (mn1 > mr1);

        // --- exp2; P packs directly into f16 A-frags ---
        uint32_t p[4][2];
        float ps0 = 0.f, ps1 = 0.f;
#pragma unroll
        for (int nt = 0; nt < 4; nt++) {
            float e0 = ex2f(sfr[nt][0] - mn0);
            float e1 = ex2f(sfr[nt][1] - mn0);
            float e2 = ex2f(sfr[nt][2] - mn1);
            float e3 = ex2f(sfr[nt][3] - mn1);
            ps0 += e0 + e1; ps1 += e2 + e3;
            p[nt][0] = packh2(e0, e1);
            p[nt][1] = packh2(e2, e3);
        }
        ps0 += __shfl_xor_sync(0xffffffffu, ps0, 1);
        ps0 += __shfl_xor_sync(0xffffffffu, ps0, 2);
        ps1 += __shfl_xor_sync(0xffffffffu, ps1, 1);
        ps1 += __shfl_xor_sync(0xffffffffu, ps1, 2);

        float al0 = ex2f(mr0 - mn0);
        float al1 = ex2f(mr1 - mn1);
        lr0 = lr0 * al0 + ps0;
        lr1 = lr1 * al1 + ps1;
        mr0 = mn0; mr1 = mn1;
        if (upd) {
#pragma unroll
            for (int nt = 0; nt < 8; nt++) {
                ofr[nt][0] *= al0; ofr[nt][1] *= al0;
                ofr[nt][2] *= al1; ofr[nt][3] *= al1;
            }
        }

        // --- O += P V (b-frags via ldmatrix on Vt [d][token]) ---
#pragma unroll
        for (int kc = 0; kc < 2; kc++) {
            uint32_t pa[4] = {p[2 * kc][0], p[2 * kc][1],
                              p[2 * kc + 1][0], p[2 * kc + 1][1]};
#pragma unroll
            for (int j = 0; j < 4; j++) {
                uint32_t b0, b1, b2, b3;
                LDSM4(b0, b1, b2, b3, vb + voff[j] + kc * 32);
                mma16(ofr[2 * j],     pa, b0, b1);
                mma16(ofr[2 * j + 1], pa, b2, b3);
            }
        }
    }

    // ---- Epilogue: merge the two wn halves; write fp16 H ----
    __syncthreads();
    if (wn == 1) {
#pragma unroll
        for (int nt = 0; nt < 8; nt++) {
            *(float2*)(obuf + (m0 + g) * 66 + nt * 8 + 2 * lq) =
                make_float2(ofr[nt][0], ofr[nt][1]);
            *(float2*)(obuf + (m0 + 8 + g) * 66 + nt * 8 + 2 * lq) =
                make_float2(ofr[nt][2], ofr[nt][3]);
        }
        if (lq == 0) {
            *(float2*)(obuf + (m0 + g) * 66 + 64) = make_float2(mr0, lr0);
            *(float2*)(obuf + (m0 + 8 + g) * 66 + 64) = make_float2(mr1, lr1);
        }
    }
    __syncthreads();
    if (wn == 0) {
        float2 ml0 = *(const float2*)(obuf + (m0 + g) * 66 + 64);
        float2 ml1 = *(const float2*)(obuf + (m0 + 8 + g) * 66 + 64);
        float M0 = fmaxf(mr0, ml0.x);
        float M1 = fmaxf(mr1, ml1.x);
        float e00 = ex2f(mr0 - M0), e01 = ex2f(ml0.x - M0);
        float e10 = ex2f(mr1 - M1), e11 = ex2f(ml1.x - M1);
        float il0 = 1.f / (lr0 * e00 + ml0.y * e01);
        float il1 = 1.f / (lr1 * e10 + ml1.y * e11);
        int n0g = qt * 64 + m0 + g;
#pragma unroll
        for (int nt = 0; nt < 8; nt++) {
            float2 oa = *(const float2*)(obuf + (m0 + g) * 66 + nt * 8 + 2 * lq);
            float2 ob = *(const float2*)(obuf + (m0 + 8 + g) * 66 + nt * 8 + 2 * lq);
            int col = h * HD + nt * 8 + 2 * lq;
            *(uint32_t*)(g_Hh + (size_t)n0g * DMODEL + col) =
                packh2((ofr[nt][0] * e00 + oa.x * e01) * il0,
                       (ofr[nt][1] * e00 + oa.y * e01) * il0);
            *(uint32_t*)(g_Hh + (size_t)(n0g + 8) * DMODEL + col) =
                packh2((ofr[nt][2] * e10 + ob.x * e11) * il1,
                       (ofr[nt][3] * e10 + ob.y * e11) * il1);
        }
    }
}

// ---------------------------------------------------------------------------
extern "C" void kernel_launch(void* const* d_in, const int* in_sizes, int n_in,
                              void* d_out, int out_size) {
    const float* q  = (const float*)d_in[0];
    const float* k  = (const float*)d_in[1];
    const float* v  = (const float*)d_in[2];
    const float* Wq = (const float*)d_in[3];
    const float* Wk = (const float*)d_in[4];
    const float* Wv = (const float*)d_in[5];
    const float* Wo = (const float*)d_in[6];

    __half* Hp; uint32_t* Wop;
    cudaGetSymbolAddress((void**)&Hp, g_Hh);
    cudaGetSymbolAddress((void**)&Wop, g_Wop);

    cudaFuncSetAttribute(gemm_fp16, cudaFuncAttributeMaxDynamicSharedMemorySize, G_SMEM);
    cudaFuncSetAttribute(flash_h3, cudaFuncAttributeMaxDynamicSharedMemorySize, FH_SMEM);

    cvt_act<<<dim3(2048, 1, 3), 256>>>(q, k, v);
    cvt_wgt<<<dim3(512, 1, 4), 256>>>(Wq, Wk, Wv, Wo);

    gemm_fp16<<<dim3(8, 32, 3), 256, G_SMEM>>>(nullptr, nullptr, nullptr, 1);

    flash_h3<<<dim3(NTOK / 64, NH), 256, FH_SMEM>>>();

    gemm_fp16<<<dim3(8, 32, 1), 256, G_SMEM>>>(Hp, Wop, (float*)d_out, 0);
}